// round 1
// baseline (speedup 1.0000x reference)
#include <cuda_runtime.h>
#include <math.h>

#define BATCH 2
#define SEQ   2048
#define DIM   1024
#define NH    16
#define HD    64
#define DFF   4096
#define MR    (BATCH*SEQ)     /* 4096 rows */
#define TD    (3*DIM)         /* 3072 */

// ---------------- scratch (static device globals; no allocation) ----------------
__device__ float g_qkv[MR * TD];       // 50 MB
__device__ float g_attn[MR * DIM];     // 16 MB
__device__ float g_attnout[MR * DIM];  // 16 MB
__device__ float g_x2[MR * DIM];       // 16 MB
__device__ float g_h[MR * DFF];        // 64 MB
__device__ float g_ff[MR * DIM];       // 16 MB

// ---------------- SGEMM: C[M,N] = A[M,K] @ W[N,K]^T + bias (opt ReLU) ----------
// 128x128 tile, BK=8, 256 threads, 8x8 microtile. All dims divisible (no guards).
template<int RELU>
__global__ void __launch_bounds__(256) sgemm_nt(const float* __restrict__ A,
                                                const float* __restrict__ W,
                                                const float* __restrict__ bias,
                                                float* __restrict__ C,
                                                int M, int N, int K)
{
    __shared__ float As[8][128];
    __shared__ float Bs[8][128];
    const int tid = threadIdx.x;
    const int bn = blockIdx.x, bm = blockIdx.y;
    const int lr = tid >> 1;          // 0..127
    const int lc = (tid & 1) << 2;    // 0 or 4
    const float* Ap = A + ((size_t)(bm * 128 + lr)) * K + lc;
    const float* Wp = W + ((size_t)(bn * 128 + lr)) * K + lc;
    const int ty = tid >> 4, tx = tid & 15;

    float acc[8][8];
#pragma unroll
    for (int i = 0; i < 8; i++)
#pragma unroll
        for (int j = 0; j < 8; j++) acc[i][j] = 0.f;

    for (int k0 = 0; k0 < K; k0 += 8) {
        float4 a = *(const float4*)(Ap + k0);
        float4 w = *(const float4*)(Wp + k0);
        As[lc + 0][lr] = a.x; As[lc + 1][lr] = a.y; As[lc + 2][lr] = a.z; As[lc + 3][lr] = a.w;
        Bs[lc + 0][lr] = w.x; Bs[lc + 1][lr] = w.y; Bs[lc + 2][lr] = w.z; Bs[lc + 3][lr] = w.w;
        __syncthreads();
#pragma unroll
        for (int kk = 0; kk < 8; kk++) {
            float4 a0 = *(const float4*)&As[kk][ty * 8];
            float4 a1 = *(const float4*)&As[kk][ty * 8 + 4];
            float4 b0 = *(const float4*)&Bs[kk][tx * 8];
            float4 b1 = *(const float4*)&Bs[kk][tx * 8 + 4];
            float ar[8] = {a0.x, a0.y, a0.z, a0.w, a1.x, a1.y, a1.z, a1.w};
            float br[8] = {b0.x, b0.y, b0.z, b0.w, b1.x, b1.y, b1.z, b1.w};
#pragma unroll
            for (int i = 0; i < 8; i++)
#pragma unroll
                for (int j = 0; j < 8; j++)
                    acc[i][j] = fmaf(ar[i], br[j], acc[i][j]);
        }
        __syncthreads();
    }

#pragma unroll
    for (int i = 0; i < 8; i++) {
        size_t row = (size_t)(bm * 128 + ty * 8 + i);
#pragma unroll
        for (int j = 0; j < 8; j += 4) {
            int col = bn * 128 + tx * 8 + j;
            float4 r;
            r.x = acc[i][j + 0] + bias[col + 0];
            r.y = acc[i][j + 1] + bias[col + 1];
            r.z = acc[i][j + 2] + bias[col + 2];
            r.w = acc[i][j + 3] + bias[col + 3];
            if (RELU) {
                r.x = fmaxf(r.x, 0.f); r.y = fmaxf(r.y, 0.f);
                r.z = fmaxf(r.z, 0.f); r.w = fmaxf(r.w, 0.f);
            }
            *(float4*)&C[row * N + col] = r;
        }
    }
}

// ---------------- banded flash attention ----------------
// Block = (b, h, 64-query tile). 256 threads (16x16), 4x4 microtiles.
// Online softmax. Smem: Q(16K) + K^T-then-P(16K) + V(16K) = 48 KB.
__global__ void __launch_bounds__(256) attn_banded(const float* __restrict__ qkv,
                                                   float* __restrict__ out,
                                                   const int* __restrict__ winp)
{
    __shared__ float Qs[64][64];
    __shared__ float KPs[64][64];   // K^T during QK, then P during PV
    __shared__ float Vs[64][64];

    const int tid = threadIdx.x;
    const int nqt = SEQ / 64;  // 32
    const int qt = blockIdx.x % nqt;
    const int h  = (blockIdx.x / nqt) % NH;
    const int b  = blockIdx.x / (nqt * NH);
    const int q0 = qt * 64;

    int wraw = *winp;
    int window = (wraw > 0 && wraw < (1 << 20)) ? wraw : (int)__int_as_float(wraw);

    const float scale = 0.125f;  // 1/sqrt(64)

    // load Q tile (scaled)
#pragma unroll
    for (int i = 0; i < 4; i++) {
        int idx = i * 256 + tid;
        int r = idx >> 4;
        int c = (idx & 15) << 2;
        float4 v = *(const float4*)&qkv[((size_t)(b * SEQ + q0 + r)) * TD + h * HD + c];
        Qs[r][c + 0] = v.x * scale; Qs[r][c + 1] = v.y * scale;
        Qs[r][c + 2] = v.z * scale; Qs[r][c + 3] = v.w * scale;
    }

    const int ty = tid >> 4, tx = tid & 15;
    float m[4], l[4], o[4][4];
#pragma unroll
    for (int qi = 0; qi < 4; qi++) {
        m[qi] = -INFINITY; l[qi] = 0.f;
#pragma unroll
        for (int dj = 0; dj < 4; dj++) o[qi][dj] = 0.f;
    }

    int kt0 = qt - 2; if (kt0 < 0) kt0 = 0;
    int kt1 = qt + 2; if (kt1 > nqt - 1) kt1 = nqt - 1;

    for (int kt = kt0; kt <= kt1; kt++) {
        const int k0 = kt * 64;
        __syncthreads();  // previous-iter P/V reads done (also orders Q load on iter 0)

        // K tile, transposed into smem: KPs[d][k]
#pragma unroll
        for (int i = 0; i < 4; i++) {
            int idx = i * 256 + tid;
            int d4 = idx >> 6;      // 0..15
            int kr = idx & 63;      // 0..63
            float4 v = *(const float4*)&qkv[((size_t)(b * SEQ + k0 + kr)) * TD + DIM + h * HD + d4 * 4];
            KPs[d4 * 4 + 0][kr] = v.x; KPs[d4 * 4 + 1][kr] = v.y;
            KPs[d4 * 4 + 2][kr] = v.z; KPs[d4 * 4 + 3][kr] = v.w;
        }
        // V tile row-major
#pragma unroll
        for (int i = 0; i < 4; i++) {
            int idx = i * 256 + tid;
            int r = idx >> 4;
            int c = (idx & 15) << 2;
            *(float4*)&Vs[r][c] =
                *(const float4*)&qkv[((size_t)(b * SEQ + k0 + r)) * TD + 2 * DIM + h * HD + c];
        }
        __syncthreads();

        // S = Q K^T (4x4 per thread)
        float sv[4][4];
#pragma unroll
        for (int qi = 0; qi < 4; qi++)
#pragma unroll
            for (int kj = 0; kj < 4; kj++) sv[qi][kj] = 0.f;
#pragma unroll
        for (int d = 0; d < 64; d++) {
            float4 kv = *(const float4*)&KPs[d][tx * 4];
            float qv[4];
#pragma unroll
            for (int qi = 0; qi < 4; qi++) qv[qi] = Qs[ty * 4 + qi][d];
#pragma unroll
            for (int qi = 0; qi < 4; qi++) {
                sv[qi][0] = fmaf(qv[qi], kv.x, sv[qi][0]);
                sv[qi][1] = fmaf(qv[qi], kv.y, sv[qi][1]);
                sv[qi][2] = fmaf(qv[qi], kv.z, sv[qi][2]);
                sv[qi][3] = fmaf(qv[qi], kv.w, sv[qi][3]);
            }
        }

        // mask + online softmax (row reductions across the 16-lane tx group)
#pragma unroll
        for (int qi = 0; qi < 4; qi++) {
            int iq = q0 + ty * 4 + qi;
            float rmax = -INFINITY;
#pragma unroll
            for (int kj = 0; kj < 4; kj++) {
                int j = k0 + tx * 4 + kj;
                int dd = iq - j; if (dd < 0) dd = -dd;
                if (dd > window) sv[qi][kj] = -INFINITY;
                rmax = fmaxf(rmax, sv[qi][kj]);
            }
#pragma unroll
            for (int off = 8; off; off >>= 1)
                rmax = fmaxf(rmax, __shfl_xor_sync(0xffffffffu, rmax, off, 16));
            float nm = fmaxf(m[qi], rmax);
            float alpha, rs = 0.f;
            if (nm == -INFINITY) {     // fully masked tile-row so far
                alpha = 1.f;
#pragma unroll
                for (int kj = 0; kj < 4; kj++) sv[qi][kj] = 0.f;
            } else {
                alpha = __expf(m[qi] - nm);   // exp(-inf)=0 handles first finite tile
#pragma unroll
                for (int kj = 0; kj < 4; kj++) {
                    float p = (sv[qi][kj] == -INFINITY) ? 0.f : __expf(sv[qi][kj] - nm);
                    sv[qi][kj] = p;
                    rs += p;
                }
            }
#pragma unroll
            for (int off = 8; off; off >>= 1)
                rs += __shfl_xor_sync(0xffffffffu, rs, off, 16);
            l[qi] = l[qi] * alpha + rs;
            m[qi] = nm;
#pragma unroll
            for (int dj = 0; dj < 4; dj++) o[qi][dj] *= alpha;
        }

        __syncthreads();   // everyone done reading KPs as K^T
        // write P over KPs
#pragma unroll
        for (int qi = 0; qi < 4; qi++)
#pragma unroll
            for (int kj = 0; kj < 4; kj++)
                KPs[ty * 4 + qi][tx * 4 + kj] = sv[qi][kj];
        __syncthreads();

        // O += P @ V
#pragma unroll
        for (int k = 0; k < 64; k++) {
            float4 vv = *(const float4*)&Vs[k][tx * 4];
#pragma unroll
            for (int qi = 0; qi < 4; qi++) {
                float p = KPs[ty * 4 + qi][k];
                o[qi][0] = fmaf(p, vv.x, o[qi][0]);
                o[qi][1] = fmaf(p, vv.y, o[qi][1]);
                o[qi][2] = fmaf(p, vv.z, o[qi][2]);
                o[qi][3] = fmaf(p, vv.w, o[qi][3]);
            }
        }
    }

    // normalize + write (B,S,H,hd) == (B,S,D) layout
#pragma unroll
    for (int qi = 0; qi < 4; qi++) {
        float inv = 1.f / l[qi];
        float4 r;
        r.x = o[qi][0] * inv; r.y = o[qi][1] * inv;
        r.z = o[qi][2] * inv; r.w = o[qi][3] * inv;
        *(float4*)&out[((size_t)(b * SEQ + q0 + ty * 4 + qi)) * DIM + h * HD + tx * 4] = r;
    }
}

// ---------------- fused residual-add + LayerNorm (one block / row) -------------
__global__ void __launch_bounds__(256) add_ln_kernel(const float* __restrict__ X,
                                                     const float* __restrict__ Y,
                                                     const float* __restrict__ g,
                                                     const float* __restrict__ bt,
                                                     float* __restrict__ out)
{
    const int row = blockIdx.x;
    const int tid = threadIdx.x;
    const size_t base = (size_t)row * DIM + tid * 4;

    float4 xv = *(const float4*)&X[base];
    float4 yv = *(const float4*)&Y[base];
    float v0 = xv.x + yv.x, v1 = xv.y + yv.y, v2 = xv.z + yv.z, v3 = xv.w + yv.w;

    float s  = v0 + v1 + v2 + v3;
    float sq = v0 * v0 + v1 * v1 + v2 * v2 + v3 * v3;
#pragma unroll
    for (int off = 16; off; off >>= 1) {
        s  += __shfl_xor_sync(0xffffffffu, s, off);
        sq += __shfl_xor_sync(0xffffffffu, sq, off);
    }
    __shared__ float ss[8], sqs[8];
    __shared__ float mu_s, ri_s;
    int w = tid >> 5;
    if ((tid & 31) == 0) { ss[w] = s; sqs[w] = sq; }
    __syncthreads();
    if (tid == 0) {
        float St = 0.f, Qt = 0.f;
#pragma unroll
        for (int i = 0; i < 8; i++) { St += ss[i]; Qt += sqs[i]; }
        float mu = St * (1.f / DIM);
        float var = Qt * (1.f / DIM) - mu * mu;
        mu_s = mu;
        ri_s = rsqrtf(var + 1e-5f);
    }
    __syncthreads();
    float mu = mu_s, ri = ri_s;

    float4 gg = *(const float4*)&g[tid * 4];
    float4 bb = *(const float4*)&bt[tid * 4];
    float4 r;
    r.x = (v0 - mu) * ri * gg.x + bb.x;
    r.y = (v1 - mu) * ri * gg.y + bb.y;
    r.z = (v2 - mu) * ri * gg.z + bb.z;
    r.w = (v3 - mu) * ri * gg.w + bb.w;
    *(float4*)&out[base] = r;
}

// ---------------- launch ----------------
extern "C" void kernel_launch(void* const* d_in, const int* in_sizes, int n_in,
                              void* d_out, int out_size)
{
    const float* x    = (const float*)d_in[0];
    const float* inw  = (const float*)d_in[1];
    const float* inb  = (const float*)d_in[2];
    const float* ow   = (const float*)d_in[3];
    const float* ob   = (const float*)d_in[4];
    const float* l1g  = (const float*)d_in[5];
    const float* l1b  = (const float*)d_in[6];
    const float* w1   = (const float*)d_in[7];
    const float* b1   = (const float*)d_in[8];
    const float* w2   = (const float*)d_in[9];
    const float* b2   = (const float*)d_in[10];
    const float* l2g  = (const float*)d_in[11];
    const float* l2b  = (const float*)d_in[12];
    const int*   win  = (const int*)d_in[13];
    float* out = (float*)d_out;

    float *qkv, *attn, *attnout, *x2, *hbuf, *ffb;
    cudaGetSymbolAddress((void**)&qkv,     g_qkv);
    cudaGetSymbolAddress((void**)&attn,    g_attn);
    cudaGetSymbolAddress((void**)&attnout, g_attnout);
    cudaGetSymbolAddress((void**)&x2,      g_x2);
    cudaGetSymbolAddress((void**)&hbuf,    g_h);
    cudaGetSymbolAddress((void**)&ffb,     g_ff);

    dim3 blk(256);

    // 1) QKV projection: (4096,1024) x (3072,1024)^T
    sgemm_nt<0><<<dim3(TD / 128, MR / 128), blk>>>(x, inw, inb, qkv, MR, TD, DIM);
    // 2) banded attention
    attn_banded<<<BATCH * NH * (SEQ / 64), blk>>>(qkv, attn, win);
    // 3) out projection
    sgemm_nt<0><<<dim3(DIM / 128, MR / 128), blk>>>(attn, ow, ob, attnout, MR, DIM, DIM);
    // 4) x2 = LN1(x + attn_out)
    add_ln_kernel<<<MR, blk>>>(x, attnout, l1g, l1b, x2);
    // 5) h = relu(x2 @ w1^T + b1)
    sgemm_nt<1><<<dim3(DFF / 128, MR / 128), blk>>>(x2, w1, b1, hbuf, MR, DFF, DIM);
    // 6) ff = h @ w2^T + b2
    sgemm_nt<0><<<dim3(DIM / 128, MR / 128), blk>>>(hbuf, w2, b2, ffb, MR, DIM, DFF);
    // 7) out = LN2(x2 + ff)
    add_ln_kernel<<<MR, blk>>>(x2, ffb, l2g, l2b, out);
}

// round 3
// speedup vs baseline: 2.9575x; 2.9575x over previous
#include <cuda_runtime.h>
#include <math.h>
#include <stdint.h>

#define BATCH 2
#define SEQ   2048
#define DIM   1024
#define NH    16
#define HD    64
#define DFF   4096
#define MR    (BATCH*SEQ)     /* 4096 rows */
#define TD    (3*DIM)         /* 3072 */

// ---------------- scratch (static device globals; no allocation) ----------------
__device__ float g_qkv[MR * TD];
__device__ float g_attn[MR * DIM];
__device__ float g_attnout[MR * DIM];
__device__ float g_x2[MR * DIM];
__device__ float g_h[MR * DFF];
__device__ float g_ff[MR * DIM];

// ---------------- TF32 tensor-core GEMM --------------------------------------
// C[M,N] = A[M,K] @ W[N,K]^T + bias (opt ReLU).
// 128x128 block tile, BK=16, 256 threads (8 warps, 2x4), warp tile 64x32.
// mma.sync m16n8k8 tf32. smem row stride 20 floats -> conflict-free frag reads.
#define BKT 16
#define SST 20   /* smem row stride in floats */

__device__ __forceinline__ uint32_t f2tf(float x) {
    uint32_t r;
    asm("cvt.rna.tf32.f32 %0, %1;" : "=r"(r) : "f"(x));
    return r;
}

__device__ __forceinline__ void mma_tf32(float* c, const uint32_t* a, const uint32_t* b) {
    asm volatile(
        "mma.sync.aligned.m16n8k8.row.col.f32.tf32.tf32.f32 "
        "{%0,%1,%2,%3}, {%4,%5,%6,%7}, {%8,%9}, {%0,%1,%2,%3};"
        : "+f"(c[0]), "+f"(c[1]), "+f"(c[2]), "+f"(c[3])
        : "r"(a[0]), "r"(a[1]), "r"(a[2]), "r"(a[3]), "r"(b[0]), "r"(b[1]));
}

template<int RELU>
__global__ void __launch_bounds__(256, 2) gemm_tf32(const float* __restrict__ A,
                                                    const float* __restrict__ W,
                                                    const float* __restrict__ bias,
                                                    float* __restrict__ C,
                                                    int M, int N, int K)
{
    __shared__ float As[2][128 * SST];
    __shared__ float Bs[2][128 * SST];

    const int tid  = threadIdx.x;
    const int wid  = tid >> 5;
    const int lane = tid & 31;
    const int g = lane >> 2;    // 0..7
    const int t = lane & 3;     // 0..3
    const int wm = wid >> 2;    // 0..1  (m offset 64*wm)
    const int wn = wid & 3;     // 0..3  (n offset 32*wn)
    const int bm0 = blockIdx.y * 128;
    const int bn0 = blockIdx.x * 128;

    float acc[4][4][4];
#pragma unroll
    for (int mi = 0; mi < 4; mi++)
#pragma unroll
        for (int ni = 0; ni < 4; ni++)
#pragma unroll
            for (int q = 0; q < 4; q++) acc[mi][ni][q] = 0.f;

    const int NT = K / BKT;

    auto issue = [&](int kt, int buf) {
        const int k0 = kt * BKT;
#pragma unroll
        for (int p = 0; p < 2; p++) {
            int idx = p * 256 + tid;
            int row = idx >> 2;
            int c4  = (idx & 3) << 2;
            uint32_t da = (uint32_t)__cvta_generic_to_shared(&As[buf][row * SST + c4]);
            const float* ga = A + (size_t)(bm0 + row) * K + k0 + c4;
            asm volatile("cp.async.cg.shared.global [%0], [%1], 16;" :: "r"(da), "l"(ga));
            uint32_t db = (uint32_t)__cvta_generic_to_shared(&Bs[buf][row * SST + c4]);
            const float* gb = W + (size_t)(bn0 + row) * K + k0 + c4;
            asm volatile("cp.async.cg.shared.global [%0], [%1], 16;" :: "r"(db), "l"(gb));
        }
        asm volatile("cp.async.commit_group;");
    };

    issue(0, 0);

    for (int kt = 0; kt < NT; kt++) {
        const int buf = kt & 1;
        if (kt + 1 < NT) {
            issue(kt + 1, buf ^ 1);
            asm volatile("cp.async.wait_group 1;");
        } else {
            asm volatile("cp.async.wait_group 0;");
        }
        __syncthreads();

#pragma unroll
        for (int ks = 0; ks < 2; ks++) {
            const int k0 = ks * 8;
            uint32_t af[4][4], bf[4][2];
#pragma unroll
            for (int mi = 0; mi < 4; mi++) {
                int r = wm * 64 + mi * 16 + g;
                af[mi][0] = f2tf(As[buf][r * SST + k0 + t]);
                af[mi][1] = f2tf(As[buf][(r + 8) * SST + k0 + t]);
                af[mi][2] = f2tf(As[buf][r * SST + k0 + 4 + t]);
                af[mi][3] = f2tf(As[buf][(r + 8) * SST + k0 + 4 + t]);
            }
#pragma unroll
            for (int ni = 0; ni < 4; ni++) {
                int n = wn * 32 + ni * 8 + g;
                bf[ni][0] = f2tf(Bs[buf][n * SST + k0 + t]);
                bf[ni][1] = f2tf(Bs[buf][n * SST + k0 + 4 + t]);
            }
#pragma unroll
            for (int mi = 0; mi < 4; mi++)
#pragma unroll
                for (int ni = 0; ni < 4; ni++)
                    mma_tf32(acc[mi][ni], af[mi], bf[ni]);
        }
        __syncthreads();
    }

    // epilogue: bias (+relu) and store
#pragma unroll
    for (int mi = 0; mi < 4; mi++) {
        int r0 = bm0 + wm * 64 + mi * 16 + g;
#pragma unroll
        for (int ni = 0; ni < 4; ni++) {
            int col = bn0 + wn * 32 + ni * 8 + 2 * t;
            float2 bb = *(const float2*)&bias[col];
            float2 v0, v1;
            v0.x = acc[mi][ni][0] + bb.x; v0.y = acc[mi][ni][1] + bb.y;
            v1.x = acc[mi][ni][2] + bb.x; v1.y = acc[mi][ni][3] + bb.y;
            if (RELU) {
                v0.x = fmaxf(v0.x, 0.f); v0.y = fmaxf(v0.y, 0.f);
                v1.x = fmaxf(v1.x, 0.f); v1.y = fmaxf(v1.y, 0.f);
            }
            *(float2*)&C[(size_t)r0 * N + col] = v0;
            *(float2*)&C[(size_t)(r0 + 8) * N + col] = v1;
        }
    }
}

// ---------------- banded flash attention (fp32) ----------------
__global__ void __launch_bounds__(256) attn_banded(const float* __restrict__ qkv,
                                                   float* __restrict__ out,
                                                   const int* __restrict__ winp)
{
    __shared__ float Qs[64][64];
    __shared__ float KPs[64][64];
    __shared__ float Vs[64][64];

    const int tid = threadIdx.x;
    const int nqt = SEQ / 64;
    const int qt = blockIdx.x % nqt;
    const int h  = (blockIdx.x / nqt) % NH;
    const int b  = blockIdx.x / (nqt * NH);
    const int q0 = qt * 64;

    int wraw = *winp;
    int window = (wraw > 0 && wraw < (1 << 20)) ? wraw : (int)__int_as_float(wraw);

    const float scale = 0.125f;

#pragma unroll
    for (int i = 0; i < 4; i++) {
        int idx = i * 256 + tid;
        int r = idx >> 4;
        int c = (idx & 15) << 2;
        float4 v = *(const float4*)&qkv[((size_t)(b * SEQ + q0 + r)) * TD + h * HD + c];
        Qs[r][c + 0] = v.x * scale; Qs[r][c + 1] = v.y * scale;
        Qs[r][c + 2] = v.z * scale; Qs[r][c + 3] = v.w * scale;
    }

    const int ty = tid >> 4, tx = tid & 15;
    float m[4], l[4], o[4][4];
#pragma unroll
    for (int qi = 0; qi < 4; qi++) {
        m[qi] = -INFINITY; l[qi] = 0.f;
#pragma unroll
        for (int dj = 0; dj < 4; dj++) o[qi][dj] = 0.f;
    }

    int kt0 = qt - 2; if (kt0 < 0) kt0 = 0;
    int kt1 = qt + 2; if (kt1 > nqt - 1) kt1 = nqt - 1;

    for (int kt = kt0; kt <= kt1; kt++) {
        const int k0 = kt * 64;
        __syncthreads();

#pragma unroll
        for (int i = 0; i < 4; i++) {
            int idx = i * 256 + tid;
            int d4 = idx >> 6;
            int kr = idx & 63;
            float4 v = *(const float4*)&qkv[((size_t)(b * SEQ + k0 + kr)) * TD + DIM + h * HD + d4 * 4];
            KPs[d4 * 4 + 0][kr] = v.x; KPs[d4 * 4 + 1][kr] = v.y;
            KPs[d4 * 4 + 2][kr] = v.z; KPs[d4 * 4 + 3][kr] = v.w;
        }
#pragma unroll
        for (int i = 0; i < 4; i++) {
            int idx = i * 256 + tid;
            int r = idx >> 4;
            int c = (idx & 15) << 2;
            *(float4*)&Vs[r][c] =
                *(const float4*)&qkv[((size_t)(b * SEQ + k0 + r)) * TD + 2 * DIM + h * HD + c];
        }
        __syncthreads();

        float sv[4][4];
#pragma unroll
        for (int qi = 0; qi < 4; qi++)
#pragma unroll
            for (int kj = 0; kj < 4; kj++) sv[qi][kj] = 0.f;
#pragma unroll
        for (int d = 0; d < 64; d++) {
            float4 kv = *(const float4*)&KPs[d][tx * 4];
            float qv[4];
#pragma unroll
            for (int qi = 0; qi < 4; qi++) qv[qi] = Qs[ty * 4 + qi][d];
#pragma unroll
            for (int qi = 0; qi < 4; qi++) {
                sv[qi][0] = fmaf(qv[qi], kv.x, sv[qi][0]);
                sv[qi][1] = fmaf(qv[qi], kv.y, sv[qi][1]);
                sv[qi][2] = fmaf(qv[qi], kv.z, sv[qi][2]);
                sv[qi][3] = fmaf(qv[qi], kv.w, sv[qi][3]);
            }
        }

#pragma unroll
        for (int qi = 0; qi < 4; qi++) {
            int iq = q0 + ty * 4 + qi;
            float rmax = -INFINITY;
#pragma unroll
            for (int kj = 0; kj < 4; kj++) {
                int j = k0 + tx * 4 + kj;
                int dd = iq - j; if (dd < 0) dd = -dd;
                if (dd > window) sv[qi][kj] = -INFINITY;
                rmax = fmaxf(rmax, sv[qi][kj]);
            }
#pragma unroll
            for (int off = 8; off; off >>= 1)
                rmax = fmaxf(rmax, __shfl_xor_sync(0xffffffffu, rmax, off, 16));
            float nm = fmaxf(m[qi], rmax);
            float alpha, rs = 0.f;
            if (nm == -INFINITY) {
                alpha = 1.f;
#pragma unroll
                for (int kj = 0; kj < 4; kj++) sv[qi][kj] = 0.f;
            } else {
                alpha = __expf(m[qi] - nm);
#pragma unroll
                for (int kj = 0; kj < 4; kj++) {
                    float p = (sv[qi][kj] == -INFINITY) ? 0.f : __expf(sv[qi][kj] - nm);
                    sv[qi][kj] = p;
                    rs += p;
                }
            }
#pragma unroll
            for (int off = 8; off; off >>= 1)
                rs += __shfl_xor_sync(0xffffffffu, rs, off, 16);
            l[qi] = l[qi] * alpha + rs;
            m[qi] = nm;
#pragma unroll
            for (int dj = 0; dj < 4; dj++) o[qi][dj] *= alpha;
        }

        __syncthreads();
#pragma unroll
        for (int qi = 0; qi < 4; qi++)
#pragma unroll
            for (int kj = 0; kj < 4; kj++)
                KPs[ty * 4 + qi][tx * 4 + kj] = sv[qi][kj];
        __syncthreads();

#pragma unroll
        for (int k = 0; k < 64; k++) {
            float4 vv = *(const float4*)&Vs[k][tx * 4];
#pragma unroll
            for (int qi = 0; qi < 4; qi++) {
                float p = KPs[ty * 4 + qi][k];
                o[qi][0] = fmaf(p, vv.x, o[qi][0]);
                o[qi][1] = fmaf(p, vv.y, o[qi][1]);
                o[qi][2] = fmaf(p, vv.z, o[qi][2]);
                o[qi][3] = fmaf(p, vv.w, o[qi][3]);
            }
        }
    }

#pragma unroll
    for (int qi = 0; qi < 4; qi++) {
        float inv = 1.f / l[qi];
        float4 r;
        r.x = o[qi][0] * inv; r.y = o[qi][1] * inv;
        r.z = o[qi][2] * inv; r.w = o[qi][3] * inv;
        *(float4*)&out[((size_t)(b * SEQ + q0 + ty * 4 + qi)) * DIM + h * HD + tx * 4] = r;
    }
}

// ---------------- fused residual-add + LayerNorm -------------
__global__ void __launch_bounds__(256) add_ln_kernel(const float* __restrict__ X,
                                                     const float* __restrict__ Y,
                                                     const float* __restrict__ g,
                                                     const float* __restrict__ bt,
                                                     float* __restrict__ out)
{
    const int row = blockIdx.x;
    const int tid = threadIdx.x;
    const size_t base = (size_t)row * DIM + tid * 4;

    float4 xv = *(const float4*)&X[base];
    float4 yv = *(const float4*)&Y[base];
    float v0 = xv.x + yv.x, v1 = xv.y + yv.y, v2 = xv.z + yv.z, v3 = xv.w + yv.w;

    float s  = v0 + v1 + v2 + v3;
    float sq = v0 * v0 + v1 * v1 + v2 * v2 + v3 * v3;
#pragma unroll
    for (int off = 16; off; off >>= 1) {
        s  += __shfl_xor_sync(0xffffffffu, s, off);
        sq += __shfl_xor_sync(0xffffffffu, sq, off);
    }
    __shared__ float ss[8], sqs[8];
    __shared__ float mu_s, ri_s;
    int w = tid >> 5;
    if ((tid & 31) == 0) { ss[w] = s; sqs[w] = sq; }
    __syncthreads();
    if (tid == 0) {
        float St = 0.f, Qt = 0.f;
#pragma unroll
        for (int i = 0; i < 8; i++) { St += ss[i]; Qt += sqs[i]; }
        float mu = St * (1.f / DIM);
        float var = Qt * (1.f / DIM) - mu * mu;
        mu_s = mu;
        ri_s = rsqrtf(var + 1e-5f);
    }
    __syncthreads();
    float mu = mu_s, ri = ri_s;

    float4 gg = *(const float4*)&g[tid * 4];
    float4 bb = *(const float4*)&bt[tid * 4];
    float4 r;
    r.x = (v0 - mu) * ri * gg.x + bb.x;
    r.y = (v1 - mu) * ri * gg.y + bb.y;
    r.z = (v2 - mu) * ri * gg.z + bb.z;
    r.w = (v3 - mu) * ri * gg.w + bb.w;
    *(float4*)&out[base] = r;
}

// ---------------- launch ----------------
extern "C" void kernel_launch(void* const* d_in, const int* in_sizes, int n_in,
                              void* d_out, int out_size)
{
    const float* x    = (const float*)d_in[0];
    const float* inw  = (const float*)d_in[1];
    const float* inb  = (const float*)d_in[2];
    const float* ow   = (const float*)d_in[3];
    const float* ob   = (const float*)d_in[4];
    const float* l1g  = (const float*)d_in[5];
    const float* l1b  = (const float*)d_in[6];
    const float* w1   = (const float*)d_in[7];
    const float* b1   = (const float*)d_in[8];
    const float* w2   = (const float*)d_in[9];
    const float* b2   = (const float*)d_in[10];
    const float* l2g  = (const float*)d_in[11];
    const float* l2b  = (const float*)d_in[12];
    const int*   win  = (const int*)d_in[13];
    float* out = (float*)d_out;

    float *qkv, *attn, *attnout, *x2, *hbuf, *ffb;
    cudaGetSymbolAddress((void**)&qkv,     g_qkv);
    cudaGetSymbolAddress((void**)&attn,    g_attn);
    cudaGetSymbolAddress((void**)&attnout, g_attnout);
    cudaGetSymbolAddress((void**)&x2,      g_x2);
    cudaGetSymbolAddress((void**)&hbuf,    g_h);
    cudaGetSymbolAddress((void**)&ffb,     g_ff);

    dim3 blk(256);

    // 1) QKV projection
    gemm_tf32<0><<<dim3(TD / 128, MR / 128), blk>>>(x, inw, inb, qkv, MR, TD, DIM);
    // 2) banded attention
    attn_banded<<<BATCH * NH * (SEQ / 64), blk>>>(qkv, attn, win);
    // 3) out projection
    gemm_tf32<0><<<dim3(DIM / 128, MR / 128), blk>>>(attn, ow, ob, attnout, MR, DIM, DIM);
    // 4) x2 = LN1(x + attn_out)
    add_ln_kernel<<<MR, blk>>>(x, attnout, l1g, l1b, x2);
    // 5) h = relu(x2 @ w1^T + b1)
    gemm_tf32<1><<<dim3(DFF / 128, MR / 128), blk>>>(x2, w1, b1, hbuf, MR, DFF, DIM);
    // 6) ff = h @ w2^T + b2
    gemm_tf32<0><<<dim3(DIM / 128, MR / 128), blk>>>(hbuf, w2, b2, ffb, MR, DIM, DFF);
    // 7) out = LN2(x2 + ff)
    add_ln_kernel<<<MR, blk>>>(x2, ffb, l2g, l2b, out);
}

// round 5
// speedup vs baseline: 3.3820x; 1.1435x over previous
#include <cuda_runtime.h>
#include <math.h>
#include <stdint.h>

#define BATCH 2
#define SEQ   2048
#define DIM   1024
#define NH    16
#define HD    64
#define DFF   4096
#define MR    (BATCH*SEQ)     /* 4096 rows */
#define TD    (3*DIM)         /* 3072 */

// ---------------- scratch (static device globals; no allocation) ----------------
__device__ float g_qkv[MR * TD];
__device__ float g_attn[MR * DIM];
__device__ float g_attnout[MR * DIM];
__device__ float g_x2[MR * DIM];
__device__ float g_h[MR * DFF];
__device__ float g_ff[MR * DIM];

// ---------------- TF32 tensor-core GEMM --------------------------------------
// C[M,N] = A[M,K] @ W[N,K]^T + bias (opt ReLU).
// 128x128 block tile, BK=32, 256 threads (8 warps, 2x4), warp tile 64x32.
// mma.sync m16n8k8 tf32, raw fp32 bits (HW ignores low mantissa bits).
// smem row stride 36 floats -> conflict-free fragment reads ((4g+t) mod 32).
#define BKG   32
#define SST   36                      /* smem row stride in floats */
#define TILEF (128 * SST)             /* floats per tile buffer */
#define GSMEM_BYTES (4 * TILEF * 4)   /* 2 bufs x (A+B) = 73728 B */

__device__ __forceinline__ void mma_tf32(float* c, const uint32_t* a, const uint32_t* b) {
    asm volatile(
        "mma.sync.aligned.m16n8k8.row.col.f32.tf32.tf32.f32 "
        "{%0,%1,%2,%3}, {%4,%5,%6,%7}, {%8,%9}, {%0,%1,%2,%3};"
        : "+f"(c[0]), "+f"(c[1]), "+f"(c[2]), "+f"(c[3])
        : "r"(a[0]), "r"(a[1]), "r"(a[2]), "r"(a[3]), "r"(b[0]), "r"(b[1]));
}

template<int RELU>
__global__ void __launch_bounds__(256, 2) gemm_tf32(const float* __restrict__ A,
                                                    const float* __restrict__ W,
                                                    const float* __restrict__ bias,
                                                    float* __restrict__ C,
                                                    int M, int N, int K)
{
    extern __shared__ float smf[];
    // layout: [buf][A tile | B tile], each TILEF floats
    const int tid  = threadIdx.x;
    const int wid  = tid >> 5;
    const int lane = tid & 31;
    const int g = lane >> 2;    // 0..7
    const int t = lane & 3;     // 0..3
    const int wm = wid >> 2;    // 0..1  (m offset 64*wm)
    const int wn = wid & 3;     // 0..3  (n offset 32*wn)
    const int bm0 = blockIdx.y * 128;
    const int bn0 = blockIdx.x * 128;

    float acc[4][4][4];
#pragma unroll
    for (int mi = 0; mi < 4; mi++)
#pragma unroll
        for (int ni = 0; ni < 4; ni++)
#pragma unroll
            for (int q = 0; q < 4; q++) acc[mi][ni][q] = 0.f;

    // loader precompute: per thread, 4 16B chunks of A + 4 of B per stage
    int lrow[4], lkc[4];
#pragma unroll
    for (int i = 0; i < 4; i++) {
        int c = tid + i * 256;        // 0..1023
        lrow[i] = c >> 3;             // 0..127
        lkc[i]  = (c & 7) << 2;       // k offset in floats (0,4,..,28)
    }

    const int NS = K / BKG;

    auto issue = [&](int kt, int buf) {
        const int k0 = kt * BKG;
        float* ab = smf + buf * 2 * TILEF;
        float* bb = ab + TILEF;
#pragma unroll
        for (int i = 0; i < 4; i++) {
            uint32_t da = (uint32_t)__cvta_generic_to_shared(&ab[lrow[i] * SST + lkc[i]]);
            const float* ga = A + (size_t)(bm0 + lrow[i]) * K + k0 + lkc[i];
            asm volatile("cp.async.cg.shared.global [%0], [%1], 16;" :: "r"(da), "l"(ga));
        }
#pragma unroll
        for (int i = 0; i < 4; i++) {
            uint32_t db = (uint32_t)__cvta_generic_to_shared(&bb[lrow[i] * SST + lkc[i]]);
            const float* gb = W + (size_t)(bn0 + lrow[i]) * K + k0 + lkc[i];
            asm volatile("cp.async.cg.shared.global [%0], [%1], 16;" :: "r"(db), "l"(gb));
        }
        asm volatile("cp.async.commit_group;");
    };

    issue(0, 0);

    for (int kt = 0; kt < NS; kt++) {
        const int buf = kt & 1;
        if (kt + 1 < NS) {
            issue(kt + 1, buf ^ 1);
            asm volatile("cp.async.wait_group 1;");
        } else {
            asm volatile("cp.async.wait_group 0;");
        }
        __syncthreads();

        const uint32_t* Au = (const uint32_t*)(smf + buf * 2 * TILEF);
        const uint32_t* Bu = Au + TILEF;

#pragma unroll
        for (int ks = 0; ks < 4; ks++) {
            const int k0 = ks * 8;
            uint32_t af[4][4], bf[4][2];
#pragma unroll
            for (int mi = 0; mi < 4; mi++) {
                int r = wm * 64 + mi * 16 + g;
                af[mi][0] = Au[r * SST + k0 + t];
                af[mi][1] = Au[(r + 8) * SST + k0 + t];
                af[mi][2] = Au[r * SST + k0 + 4 + t];
                af[mi][3] = Au[(r + 8) * SST + k0 + 4 + t];
            }
#pragma unroll
            for (int ni = 0; ni < 4; ni++) {
                int n = wn * 32 + ni * 8 + g;
                bf[ni][0] = Bu[n * SST + k0 + t];
                bf[ni][1] = Bu[n * SST + k0 + 4 + t];
            }
#pragma unroll
            for (int mi = 0; mi < 4; mi++)
#pragma unroll
                for (int ni = 0; ni < 4; ni++)
                    mma_tf32(acc[mi][ni], af[mi], bf[ni]);
        }
        __syncthreads();
    }

    // epilogue: bias (+relu) and store
#pragma unroll
    for (int mi = 0; mi < 4; mi++) {
        int r0 = bm0 + wm * 64 + mi * 16 + g;
#pragma unroll
        for (int ni = 0; ni < 4; ni++) {
            int col = bn0 + wn * 32 + ni * 8 + 2 * t;
            float2 bb = *(const float2*)&bias[col];
            float2 v0, v1;
            v0.x = acc[mi][ni][0] + bb.x; v0.y = acc[mi][ni][1] + bb.y;
            v1.x = acc[mi][ni][2] + bb.x; v1.y = acc[mi][ni][3] + bb.y;
            if (RELU) {
                v0.x = fmaxf(v0.x, 0.f); v0.y = fmaxf(v0.y, 0.f);
                v1.x = fmaxf(v1.x, 0.f); v1.y = fmaxf(v1.y, 0.f);
            }
            *(float2*)&C[(size_t)r0 * N + col] = v0;
            *(float2*)&C[(size_t)(r0 + 8) * N + col] = v1;
        }
    }
}

// ---------------- banded flash attention (fp32, unchanged) ----------------
__global__ void __launch_bounds__(256) attn_banded(const float* __restrict__ qkv,
                                                   float* __restrict__ out,
                                                   const int* __restrict__ winp)
{
    __shared__ float Qs[64][64];
    __shared__ float KPs[64][64];
    __shared__ float Vs[64][64];

    const int tid = threadIdx.x;
    const int nqt = SEQ / 64;
    const int qt = blockIdx.x % nqt;
    const int h  = (blockIdx.x / nqt) % NH;
    const int b  = blockIdx.x / (nqt * NH);
    const int q0 = qt * 64;

    int wraw = *winp;
    int window = (wraw > 0 && wraw < (1 << 20)) ? wraw : (int)__int_as_float(wraw);

    const float scale = 0.125f;

#pragma unroll
    for (int i = 0; i < 4; i++) {
        int idx = i * 256 + tid;
        int r = idx >> 4;
        int c = (idx & 15) << 2;
        float4 v = *(const float4*)&qkv[((size_t)(b * SEQ + q0 + r)) * TD + h * HD + c];
        Qs[r][c + 0] = v.x * scale; Qs[r][c + 1] = v.y * scale;
        Qs[r][c + 2] = v.z * scale; Qs[r][c + 3] = v.w * scale;
    }

    const int ty = tid >> 4, tx = tid & 15;
    float m[4], l[4], o[4][4];
#pragma unroll
    for (int qi = 0; qi < 4; qi++) {
        m[qi] = -INFINITY; l[qi] = 0.f;
#pragma unroll
        for (int dj = 0; dj < 4; dj++) o[qi][dj] = 0.f;
    }

    int kt0 = qt - 2; if (kt0 < 0) kt0 = 0;
    int kt1 = qt + 2; if (kt1 > nqt - 1) kt1 = nqt - 1;

    for (int kt = kt0; kt <= kt1; kt++) {
        const int k0 = kt * 64;
        __syncthreads();

#pragma unroll
        for (int i = 0; i < 4; i++) {
            int idx = i * 256 + tid;
            int d4 = idx >> 6;
            int kr = idx & 63;
            float4 v = *(const float4*)&qkv[((size_t)(b * SEQ + k0 + kr)) * TD + DIM + h * HD + d4 * 4];
            KPs[d4 * 4 + 0][kr] = v.x; KPs[d4 * 4 + 1][kr] = v.y;
            KPs[d4 * 4 + 2][kr] = v.z; KPs[d4 * 4 + 3][kr] = v.w;
        }
#pragma unroll
        for (int i = 0; i < 4; i++) {
            int idx = i * 256 + tid;
            int r = idx >> 4;
            int c = (idx & 15) << 2;
            *(float4*)&Vs[r][c] =
                *(const float4*)&qkv[((size_t)(b * SEQ + k0 + r)) * TD + 2 * DIM + h * HD + c];
        }
        __syncthreads();

        float sv[4][4];
#pragma unroll
        for (int qi = 0; qi < 4; qi++)
#pragma unroll
            for (int kj = 0; kj < 4; kj++) sv[qi][kj] = 0.f;
#pragma unroll
        for (int d = 0; d < 64; d++) {
            float4 kv = *(const float4*)&KPs[d][tx * 4];
            float qv[4];
#pragma unroll
            for (int qi = 0; qi < 4; qi++) qv[qi] = Qs[ty * 4 + qi][d];
#pragma unroll
            for (int qi = 0; qi < 4; qi++) {
                sv[qi][0] = fmaf(qv[qi], kv.x, sv[qi][0]);
                sv[qi][1] = fmaf(qv[qi], kv.y, sv[qi][1]);
                sv[qi][2] = fmaf(qv[qi], kv.z, sv[qi][2]);
                sv[qi][3] = fmaf(qv[qi], kv.w, sv[qi][3]);
            }
        }

#pragma unroll
        for (int qi = 0; qi < 4; qi++) {
            int iq = q0 + ty * 4 + qi;
            float rmax = -INFINITY;
#pragma unroll
            for (int kj = 0; kj < 4; kj++) {
                int j = k0 + tx * 4 + kj;
                int dd = iq - j; if (dd < 0) dd = -dd;
                if (dd > window) sv[qi][kj] = -INFINITY;
                rmax = fmaxf(rmax, sv[qi][kj]);
            }
#pragma unroll
            for (int off = 8; off; off >>= 1)
                rmax = fmaxf(rmax, __shfl_xor_sync(0xffffffffu, rmax, off, 16));
            float nm = fmaxf(m[qi], rmax);
            float alpha, rs = 0.f;
            if (nm == -INFINITY) {
                alpha = 1.f;
#pragma unroll
                for (int kj = 0; kj < 4; kj++) sv[qi][kj] = 0.f;
            } else {
                alpha = __expf(m[qi] - nm);
#pragma unroll
                for (int kj = 0; kj < 4; kj++) {
                    float p = (sv[qi][kj] == -INFINITY) ? 0.f : __expf(sv[qi][kj] - nm);
                    sv[qi][kj] = p;
                    rs += p;
                }
            }
#pragma unroll
            for (int off = 8; off; off >>= 1)
                rs += __shfl_xor_sync(0xffffffffu, rs, off, 16);
            l[qi] = l[qi] * alpha + rs;
            m[qi] = nm;
#pragma unroll
            for (int dj = 0; dj < 4; dj++) o[qi][dj] *= alpha;
        }

        __syncthreads();
#pragma unroll
        for (int qi = 0; qi < 4; qi++)
#pragma unroll
            for (int kj = 0; kj < 4; kj++)
                KPs[ty * 4 + qi][tx * 4 + kj] = sv[qi][kj];
        __syncthreads();

#pragma unroll
        for (int k = 0; k < 64; k++) {
            float4 vv = *(const float4*)&Vs[k][tx * 4];
#pragma unroll
            for (int qi = 0; qi < 4; qi++) {
                float p = KPs[ty * 4 + qi][k];
                o[qi][0] = fmaf(p, vv.x, o[qi][0]);
                o[qi][1] = fmaf(p, vv.y, o[qi][1]);
                o[qi][2] = fmaf(p, vv.z, o[qi][2]);
                o[qi][3] = fmaf(p, vv.w, o[qi][3]);
            }
        }
    }

#pragma unroll
    for (int qi = 0; qi < 4; qi++) {
        float inv = 1.f / l[qi];
        float4 r;
        r.x = o[qi][0] * inv; r.y = o[qi][1] * inv;
        r.z = o[qi][2] * inv; r.w = o[qi][3] * inv;
        *(float4*)&out[((size_t)(b * SEQ + q0 + ty * 4 + qi)) * DIM + h * HD + tx * 4] = r;
    }
}

// ---------------- fused residual-add + LayerNorm -------------
__global__ void __launch_bounds__(256) add_ln_kernel(const float* __restrict__ X,
                                                     const float* __restrict__ Y,
                                                     const float* __restrict__ g,
                                                     const float* __restrict__ bt,
                                                     float* __restrict__ out)
{
    const int row = blockIdx.x;
    const int tid = threadIdx.x;
    const size_t base = (size_t)row * DIM + tid * 4;

    float4 xv = *(const float4*)&X[base];
    float4 yv = *(const float4*)&Y[base];
    float v0 = xv.x + yv.x, v1 = xv.y + yv.y, v2 = xv.z + yv.z, v3 = xv.w + yv.w;

    float s  = v0 + v1 + v2 + v3;
    float sq = v0 * v0 + v1 * v1 + v2 * v2 + v3 * v3;
#pragma unroll
    for (int off = 16; off; off >>= 1) {
        s  += __shfl_xor_sync(0xffffffffu, s, off);
        sq += __shfl_xor_sync(0xffffffffu, sq, off);
    }
    __shared__ float ss[8], sqs[8];
    __shared__ float mu_s, ri_s;
    int w = tid >> 5;
    if ((tid & 31) == 0) { ss[w] = s; sqs[w] = sq; }
    __syncthreads();
    if (tid == 0) {
        float St = 0.f, Qt = 0.f;
#pragma unroll
        for (int i = 0; i < 8; i++) { St += ss[i]; Qt += sqs[i]; }
        float mu = St * (1.f / DIM);
        float var = Qt * (1.f / DIM) - mu * mu;
        mu_s = mu;
        ri_s = rsqrtf(var + 1e-5f);
    }
    __syncthreads();
    float mu = mu_s, ri = ri_s;

    float4 gg = *(const float4*)&g[tid * 4];
    float4 bb = *(const float4*)&bt[tid * 4];
    float4 r;
    r.x = (v0 - mu) * ri * gg.x + bb.x;
    r.y = (v1 - mu) * ri * gg.y + bb.y;
    r.z = (v2 - mu) * ri * gg.z + bb.z;
    r.w = (v3 - mu) * ri * gg.w + bb.w;
    *(float4*)&out[base] = r;
}

// ---------------- launch ----------------
extern "C" void kernel_launch(void* const* d_in, const int* in_sizes, int n_in,
                              void* d_out, int out_size)
{
    const float* x    = (const float*)d_in[0];
    const float* inw  = (const float*)d_in[1];
    const float* inb  = (const float*)d_in[2];
    const float* ow   = (const float*)d_in[3];
    const float* ob   = (const float*)d_in[4];
    const float* l1g  = (const float*)d_in[5];
    const float* l1b  = (const float*)d_in[6];
    const float* w1   = (const float*)d_in[7];
    const float* b1   = (const float*)d_in[8];
    const float* w2   = (const float*)d_in[9];
    const float* b2   = (const float*)d_in[10];
    const float* l2g  = (const float*)d_in[11];
    const float* l2b  = (const float*)d_in[12];
    const int*   win  = (const int*)d_in[13];
    float* out = (float*)d_out;

    float *qkv, *attn, *attnout, *x2, *hbuf, *ffb;
    cudaGetSymbolAddress((void**)&qkv,     g_qkv);
    cudaGetSymbolAddress((void**)&attn,    g_attn);
    cudaGetSymbolAddress((void**)&attnout, g_attnout);
    cudaGetSymbolAddress((void**)&x2,      g_x2);
    cudaGetSymbolAddress((void**)&hbuf,    g_h);
    cudaGetSymbolAddress((void**)&ffb,     g_ff);

    cudaFuncSetAttribute(gemm_tf32<0>, cudaFuncAttributeMaxDynamicSharedMemorySize, GSMEM_BYTES);
    cudaFuncSetAttribute(gemm_tf32<1>, cudaFuncAttributeMaxDynamicSharedMemorySize, GSMEM_BYTES);

    dim3 blk(256);

    // 1) QKV projection
    gemm_tf32<0><<<dim3(TD / 128, MR / 128), blk, GSMEM_BYTES>>>(x, inw, inb, qkv, MR, TD, DIM);
    // 2) banded attention
    attn_banded<<<BATCH * NH * (SEQ / 64), blk>>>(qkv, attn, win);
    // 3) out projection
    gemm_tf32<0><<<dim3(DIM / 128, MR / 128), blk, GSMEM_BYTES>>>(attn, ow, ob, attnout, MR, DIM, DIM);
    // 4) x2 = LN1(x + attn_out)
    add_ln_kernel<<<MR, blk>>>(x, attnout, l1g, l1b, x2);
    // 5) h = relu(x2 @ w1^T + b1)
    gemm_tf32<1><<<dim3(DFF / 128, MR / 128), blk, GSMEM_BYTES>>>(x2, w1, b1, hbuf, MR, DFF, DIM);
    // 6) ff = h @ w2^T + b2
    gemm_tf32<0><<<dim3(DIM / 128, MR / 128), blk, GSMEM_BYTES>>>(hbuf, w2, b2, ffb, MR, DIM, DFF);
    // 7) out = LN2(x2 + ff)
    add_ln_kernel<<<MR, blk>>>(x2, ffb, l2g, l2b, out);
}

// round 6
// speedup vs baseline: 3.4389x; 1.0168x over previous
#include <cuda_runtime.h>
#include <math.h>
#include <stdint.h>

#define BATCH 2
#define SEQ   2048
#define DIM   1024
#define NH    16
#define HD    64
#define DFF   4096
#define MR    (BATCH*SEQ)     /* 4096 rows */
#define TD    (3*DIM)         /* 3072 */

// ---------------- scratch (static device globals; no allocation) ----------------
__device__ float g_qkv[MR * TD];
__device__ float g_attn[MR * DIM];
__device__ float g_attnout[MR * DIM];
__device__ float g_x2[MR * DIM];
__device__ float g_h[MR * DFF];
__device__ float g_ff[MR * DIM];

// ---------------- TF32 tensor-core GEMM --------------------------------------
// C[M,N] = A[M,K] @ W[N,K]^T + bias (opt ReLU).
// 128x128 block tile, BK=32, 128 threads (4 warps, 2x2), warp tile 64x64.
// mma.sync m16n8k8 tf32, raw fp32 bits (HW ignores low mantissa bits).
// smem row stride 36 floats -> conflict-free fragment reads ((4g+t) mod 32).
#define BKG   32
#define SST   36                      /* smem row stride in floats */
#define TILEF (128 * SST)             /* floats per tile buffer */
#define GSMEM_BYTES (4 * TILEF * 4)   /* 2 bufs x (A+B) = 73728 B */

__device__ __forceinline__ void mma_tf32(float* c, const uint32_t* a, const uint32_t* b) {
    asm volatile(
        "mma.sync.aligned.m16n8k8.row.col.f32.tf32.tf32.f32 "
        "{%0,%1,%2,%3}, {%4,%5,%6,%7}, {%8,%9}, {%0,%1,%2,%3};"
        : "+f"(c[0]), "+f"(c[1]), "+f"(c[2]), "+f"(c[3])
        : "r"(a[0]), "r"(a[1]), "r"(a[2]), "r"(a[3]), "r"(b[0]), "r"(b[1]));
}

template<int RELU>
__global__ void __launch_bounds__(128, 2) gemm_tf32(const float* __restrict__ A,
                                                    const float* __restrict__ W,
                                                    const float* __restrict__ bias,
                                                    float* __restrict__ C,
                                                    int M, int N, int K)
{
    extern __shared__ float smf[];
    // layout: [buf][A tile | B tile], each TILEF floats
    const int tid  = threadIdx.x;
    const int wid  = tid >> 5;
    const int lane = tid & 31;
    const int g = lane >> 2;    // 0..7
    const int t = lane & 3;     // 0..3
    const int wm = wid >> 1;    // 0..1  (m offset 64*wm)
    const int wn = wid & 1;     // 0..1  (n offset 64*wn)
    const int bm0 = blockIdx.y * 128;
    const int bn0 = blockIdx.x * 128;

    float acc[4][8][4];
#pragma unroll
    for (int mi = 0; mi < 4; mi++)
#pragma unroll
        for (int ni = 0; ni < 8; ni++)
#pragma unroll
            for (int q = 0; q < 4; q++) acc[mi][ni][q] = 0.f;

    // loader precompute: per thread, 8 16B chunks of A + 8 of B per stage
    int lrow[8], lkc[8];
#pragma unroll
    for (int i = 0; i < 8; i++) {
        int c = tid + i * 128;        // 0..1023
        lrow[i] = c >> 3;             // 0..127
        lkc[i]  = (c & 7) << 2;       // k offset in floats (0,4,..,28)
    }

    const int NS = K / BKG;

    auto issue = [&](int kt, int buf) {
        const int k0 = kt * BKG;
        float* ab = smf + buf * 2 * TILEF;
        float* bb = ab + TILEF;
#pragma unroll
        for (int i = 0; i < 8; i++) {
            uint32_t da = (uint32_t)__cvta_generic_to_shared(&ab[lrow[i] * SST + lkc[i]]);
            const float* ga = A + (size_t)(bm0 + lrow[i]) * K + k0 + lkc[i];
            asm volatile("cp.async.cg.shared.global [%0], [%1], 16;" :: "r"(da), "l"(ga));
        }
#pragma unroll
        for (int i = 0; i < 8; i++) {
            uint32_t db = (uint32_t)__cvta_generic_to_shared(&bb[lrow[i] * SST + lkc[i]]);
            const float* gb = W + (size_t)(bn0 + lrow[i]) * K + k0 + lkc[i];
            asm volatile("cp.async.cg.shared.global [%0], [%1], 16;" :: "r"(db), "l"(gb));
        }
        asm volatile("cp.async.commit_group;");
    };

    issue(0, 0);

    for (int kt = 0; kt < NS; kt++) {
        const int buf = kt & 1;
        if (kt + 1 < NS) {
            issue(kt + 1, buf ^ 1);
            asm volatile("cp.async.wait_group 1;");
        } else {
            asm volatile("cp.async.wait_group 0;");
        }
        __syncthreads();

        const uint32_t* Au = (const uint32_t*)(smf + buf * 2 * TILEF);
        const uint32_t* Bu = Au + TILEF;

#pragma unroll
        for (int ks = 0; ks < 4; ks++) {
            const int k0 = ks * 8;
            uint32_t af[4][4], bf[8][2];
#pragma unroll
            for (int mi = 0; mi < 4; mi++) {
                int r = wm * 64 + mi * 16 + g;
                af[mi][0] = Au[r * SST + k0 + t];
                af[mi][1] = Au[(r + 8) * SST + k0 + t];
                af[mi][2] = Au[r * SST + k0 + 4 + t];
                af[mi][3] = Au[(r + 8) * SST + k0 + 4 + t];
            }
#pragma unroll
            for (int ni = 0; ni < 8; ni++) {
                int n = wn * 64 + ni * 8 + g;
                bf[ni][0] = Bu[n * SST + k0 + t];
                bf[ni][1] = Bu[n * SST + k0 + 4 + t];
            }
#pragma unroll
            for (int mi = 0; mi < 4; mi++)
#pragma unroll
                for (int ni = 0; ni < 8; ni++)
                    mma_tf32(acc[mi][ni], af[mi], bf[ni]);
        }
        __syncthreads();
    }

    // epilogue: bias (+relu) and store
#pragma unroll
    for (int mi = 0; mi < 4; mi++) {
        int r0 = bm0 + wm * 64 + mi * 16 + g;
#pragma unroll
        for (int ni = 0; ni < 8; ni++) {
            int col = bn0 + wn * 64 + ni * 8 + 2 * t;
            float2 bb = *(const float2*)&bias[col];
            float2 v0, v1;
            v0.x = acc[mi][ni][0] + bb.x; v0.y = acc[mi][ni][1] + bb.y;
            v1.x = acc[mi][ni][2] + bb.x; v1.y = acc[mi][ni][3] + bb.y;
            if (RELU) {
                v0.x = fmaxf(v0.x, 0.f); v0.y = fmaxf(v0.y, 0.f);
                v1.x = fmaxf(v1.x, 0.f); v1.y = fmaxf(v1.y, 0.f);
            }
            *(float2*)&C[(size_t)r0 * N + col] = v0;
            *(float2*)&C[(size_t)(r0 + 8) * N + col] = v1;
        }
    }
}

// ---------------- banded flash attention (fp32, unchanged) ----------------
__global__ void __launch_bounds__(256) attn_banded(const float* __restrict__ qkv,
                                                   float* __restrict__ out,
                                                   const int* __restrict__ winp)
{
    __shared__ float Qs[64][64];
    __shared__ float KPs[64][64];
    __shared__ float Vs[64][64];

    const int tid = threadIdx.x;
    const int nqt = SEQ / 64;
    const int qt = blockIdx.x % nqt;
    const int h  = (blockIdx.x / nqt) % NH;
    const int b  = blockIdx.x / (nqt * NH);
    const int q0 = qt * 64;

    int wraw = *winp;
    int window = (wraw > 0 && wraw < (1 << 20)) ? wraw : (int)__int_as_float(wraw);

    const float scale = 0.125f;

#pragma unroll
    for (int i = 0; i < 4; i++) {
        int idx = i * 256 + tid;
        int r = idx >> 4;
        int c = (idx & 15) << 2;
        float4 v = *(const float4*)&qkv[((size_t)(b * SEQ + q0 + r)) * TD + h * HD + c];
        Qs[r][c + 0] = v.x * scale; Qs[r][c + 1] = v.y * scale;
        Qs[r][c + 2] = v.z * scale; Qs[r][c + 3] = v.w * scale;
    }

    const int ty = tid >> 4, tx = tid & 15;
    float m[4], l[4], o[4][4];
#pragma unroll
    for (int qi = 0; qi < 4; qi++) {
        m[qi] = -INFINITY; l[qi] = 0.f;
#pragma unroll
        for (int dj = 0; dj < 4; dj++) o[qi][dj] = 0.f;
    }

    int kt0 = qt - 2; if (kt0 < 0) kt0 = 0;
    int kt1 = qt + 2; if (kt1 > nqt - 1) kt1 = nqt - 1;

    for (int kt = kt0; kt <= kt1; kt++) {
        const int k0 = kt * 64;
        __syncthreads();

#pragma unroll
        for (int i = 0; i < 4; i++) {
            int idx = i * 256 + tid;
            int d4 = idx >> 6;
            int kr = idx & 63;
            float4 v = *(const float4*)&qkv[((size_t)(b * SEQ + k0 + kr)) * TD + DIM + h * HD + d4 * 4];
            KPs[d4 * 4 + 0][kr] = v.x; KPs[d4 * 4 + 1][kr] = v.y;
            KPs[d4 * 4 + 2][kr] = v.z; KPs[d4 * 4 + 3][kr] = v.w;
        }
#pragma unroll
        for (int i = 0; i < 4; i++) {
            int idx = i * 256 + tid;
            int r = idx >> 4;
            int c = (idx & 15) << 2;
            *(float4*)&Vs[r][c] =
                *(const float4*)&qkv[((size_t)(b * SEQ + k0 + r)) * TD + 2 * DIM + h * HD + c];
        }
        __syncthreads();

        float sv[4][4];
#pragma unroll
        for (int qi = 0; qi < 4; qi++)
#pragma unroll
            for (int kj = 0; kj < 4; kj++) sv[qi][kj] = 0.f;
#pragma unroll
        for (int d = 0; d < 64; d++) {
            float4 kv = *(const float4*)&KPs[d][tx * 4];
            float qv[4];
#pragma unroll
            for (int qi = 0; qi < 4; qi++) qv[qi] = Qs[ty * 4 + qi][d];
#pragma unroll
            for (int qi = 0; qi < 4; qi++) {
                sv[qi][0] = fmaf(qv[qi], kv.x, sv[qi][0]);
                sv[qi][1] = fmaf(qv[qi], kv.y, sv[qi][1]);
                sv[qi][2] = fmaf(qv[qi], kv.z, sv[qi][2]);
                sv[qi][3] = fmaf(qv[qi], kv.w, sv[qi][3]);
            }
        }

#pragma unroll
        for (int qi = 0; qi < 4; qi++) {
            int iq = q0 + ty * 4 + qi;
            float rmax = -INFINITY;
#pragma unroll
            for (int kj = 0; kj < 4; kj++) {
                int j = k0 + tx * 4 + kj;
                int dd = iq - j; if (dd < 0) dd = -dd;
                if (dd > window) sv[qi][kj] = -INFINITY;
                rmax = fmaxf(rmax, sv[qi][kj]);
            }
#pragma unroll
            for (int off = 8; off; off >>= 1)
                rmax = fmaxf(rmax, __shfl_xor_sync(0xffffffffu, rmax, off, 16));
            float nm = fmaxf(m[qi], rmax);
            float alpha, rs = 0.f;
            if (nm == -INFINITY) {
                alpha = 1.f;
#pragma unroll
                for (int kj = 0; kj < 4; kj++) sv[qi][kj] = 0.f;
            } else {
                alpha = __expf(m[qi] - nm);
#pragma unroll
                for (int kj = 0; kj < 4; kj++) {
                    float p = (sv[qi][kj] == -INFINITY) ? 0.f : __expf(sv[qi][kj] - nm);
                    sv[qi][kj] = p;
                    rs += p;
                }
            }
#pragma unroll
            for (int off = 8; off; off >>= 1)
                rs += __shfl_xor_sync(0xffffffffu, rs, off, 16);
            l[qi] = l[qi] * alpha + rs;
            m[qi] = nm;
#pragma unroll
            for (int dj = 0; dj < 4; dj++) o[qi][dj] *= alpha;
        }

        __syncthreads();
#pragma unroll
        for (int qi = 0; qi < 4; qi++)
#pragma unroll
            for (int kj = 0; kj < 4; kj++)
                KPs[ty * 4 + qi][tx * 4 + kj] = sv[qi][kj];
        __syncthreads();

#pragma unroll
        for (int k = 0; k < 64; k++) {
            float4 vv = *(const float4*)&Vs[k][tx * 4];
#pragma unroll
            for (int qi = 0; qi < 4; qi++) {
                float p = KPs[ty * 4 + qi][k];
                o[qi][0] = fmaf(p, vv.x, o[qi][0]);
                o[qi][1] = fmaf(p, vv.y, o[qi][1]);
                o[qi][2] = fmaf(p, vv.z, o[qi][2]);
                o[qi][3] = fmaf(p, vv.w, o[qi][3]);
            }
        }
    }

#pragma unroll
    for (int qi = 0; qi < 4; qi++) {
        float inv = 1.f / l[qi];
        float4 r;
        r.x = o[qi][0] * inv; r.y = o[qi][1] * inv;
        r.z = o[qi][2] * inv; r.w = o[qi][3] * inv;
        *(float4*)&out[((size_t)(b * SEQ + q0 + ty * 4 + qi)) * DIM + h * HD + tx * 4] = r;
    }
}

// ---------------- fused residual-add + LayerNorm -------------
__global__ void __launch_bounds__(256) add_ln_kernel(const float* __restrict__ X,
                                                     const float* __restrict__ Y,
                                                     const float* __restrict__ g,
                                                     const float* __restrict__ bt,
                                                     float* __restrict__ out)
{
    const int row = blockIdx.x;
    const int tid = threadIdx.x;
    const size_t base = (size_t)row * DIM + tid * 4;

    float4 xv = *(const float4*)&X[base];
    float4 yv = *(const float4*)&Y[base];
    float v0 = xv.x + yv.x, v1 = xv.y + yv.y, v2 = xv.z + yv.z, v3 = xv.w + yv.w;

    float s  = v0 + v1 + v2 + v3;
    float sq = v0 * v0 + v1 * v1 + v2 * v2 + v3 * v3;
#pragma unroll
    for (int off = 16; off; off >>= 1) {
        s  += __shfl_xor_sync(0xffffffffu, s, off);
        sq += __shfl_xor_sync(0xffffffffu, sq, off);
    }
    __shared__ float ss[8], sqs[8];
    __shared__ float mu_s, ri_s;
    int w = tid >> 5;
    if ((tid & 31) == 0) { ss[w] = s; sqs[w] = sq; }
    __syncthreads();
    if (tid == 0) {
        float St = 0.f, Qt = 0.f;
#pragma unroll
        for (int i = 0; i < 8; i++) { St += ss[i]; Qt += sqs[i]; }
        float mu = St * (1.f / DIM);
        float var = Qt * (1.f / DIM) - mu * mu;
        mu_s = mu;
        ri_s = rsqrtf(var + 1e-5f);
    }
    __syncthreads();
    float mu = mu_s, ri = ri_s;

    float4 gg = *(const float4*)&g[tid * 4];
    float4 bb = *(const float4*)&bt[tid * 4];
    float4 r;
    r.x = (v0 - mu) * ri * gg.x + bb.x;
    r.y = (v1 - mu) * ri * gg.y + bb.y;
    r.z = (v2 - mu) * ri * gg.z + bb.z;
    r.w = (v3 - mu) * ri * gg.w + bb.w;
    *(float4*)&out[base] = r;
}

// ---------------- launch ----------------
extern "C" void kernel_launch(void* const* d_in, const int* in_sizes, int n_in,
                              void* d_out, int out_size)
{
    const float* x    = (const float*)d_in[0];
    const float* inw  = (const float*)d_in[1];
    const float* inb  = (const float*)d_in[2];
    const float* ow   = (const float*)d_in[3];
    const float* ob   = (const float*)d_in[4];
    const float* l1g  = (const float*)d_in[5];
    const float* l1b  = (const float*)d_in[6];
    const float* w1   = (const float*)d_in[7];
    const float* b1   = (const float*)d_in[8];
    const float* w2   = (const float*)d_in[9];
    const float* b2   = (const float*)d_in[10];
    const float* l2g  = (const float*)d_in[11];
    const float* l2b  = (const float*)d_in[12];
    const int*   win  = (const int*)d_in[13];
    float* out = (float*)d_out;

    float *qkv, *attn, *attnout, *x2, *hbuf, *ffb;
    cudaGetSymbolAddress((void**)&qkv,     g_qkv);
    cudaGetSymbolAddress((void**)&attn,    g_attn);
    cudaGetSymbolAddress((void**)&attnout, g_attnout);
    cudaGetSymbolAddress((void**)&x2,      g_x2);
    cudaGetSymbolAddress((void**)&hbuf,    g_h);
    cudaGetSymbolAddress((void**)&ffb,     g_ff);

    cudaFuncSetAttribute(gemm_tf32<0>, cudaFuncAttributeMaxDynamicSharedMemorySize, GSMEM_BYTES);
    cudaFuncSetAttribute(gemm_tf32<1>, cudaFuncAttributeMaxDynamicSharedMemorySize, GSMEM_BYTES);

    dim3 gblk(128);
    dim3 blk(256);

    // 1) QKV projection
    gemm_tf32<0><<<dim3(TD / 128, MR / 128), gblk, GSMEM_BYTES>>>(x, inw, inb, qkv, MR, TD, DIM);
    // 2) banded attention
    attn_banded<<<BATCH * NH * (SEQ / 64), blk>>>(qkv, attn, win);
    // 3) out projection
    gemm_tf32<0><<<dim3(DIM / 128, MR / 128), gblk, GSMEM_BYTES>>>(attn, ow, ob, attnout, MR, DIM, DIM);
    // 4) x2 = LN1(x + attn_out)
    add_ln_kernel<<<MR, blk>>>(x, attnout, l1g, l1b, x2);
    // 5) h = relu(x2 @ w1^T + b1)
    gemm_tf32<1><<<dim3(DFF / 128, MR / 128), gblk, GSMEM_BYTES>>>(x2, w1, b1, hbuf, MR, DFF, DIM);
    // 6) ff = h @ w2^T + b2
    gemm_tf32<0><<<dim3(DIM / 128, MR / 128), gblk, GSMEM_BYTES>>>(hbuf, w2, b2, ffb, MR, DIM, DFF);
    // 7) out = LN2(x2 + ff)
    add_ln_kernel<<<MR, blk>>>(x2, ffb, l2g, l2b, out);
}

// round 8
// speedup vs baseline: 3.6262x; 1.0545x over previous
#include <cuda_runtime.h>
#include <math.h>
#include <stdint.h>

#define BATCH 2
#define SEQ   2048
#define DIM   1024
#define NH    16
#define HD    64
#define DFF   4096
#define MR    (BATCH*SEQ)     /* 4096 rows */
#define TD    (3*DIM)         /* 3072 */

// ---------------- scratch (static device globals; no allocation) ----------------
__device__ float g_qkv[MR * TD];
__device__ float g_attn[MR * DIM];
__device__ float g_attnout[MR * DIM];
__device__ float g_x2[MR * DIM];
__device__ float g_h[MR * DFF];
__device__ float g_ff[MR * DIM];

__device__ __forceinline__ uint32_t f2tf(float x) {
    uint32_t r;
    asm("cvt.rna.tf32.f32 %0, %1;" : "=r"(r) : "f"(x));
    return r;
}
__device__ __forceinline__ float tf32r(float x) { return __uint_as_float(f2tf(x)); }

__device__ __forceinline__ void mma_tf32(float* c, const uint32_t* a, const uint32_t* b) {
    asm volatile(
        "mma.sync.aligned.m16n8k8.row.col.f32.tf32.tf32.f32 "
        "{%0,%1,%2,%3}, {%4,%5,%6,%7}, {%8,%9}, {%0,%1,%2,%3};"
        : "+f"(c[0]), "+f"(c[1]), "+f"(c[2]), "+f"(c[3])
        : "r"(a[0]), "r"(a[1]), "r"(a[2]), "r"(a[3]), "r"(b[0]), "r"(b[1]));
}

// ---------------- TF32 tensor-core GEMM (unchanged from R6) ------------------
#define BKG   32
#define SST   36
#define TILEF (128 * SST)
#define GSMEM_BYTES (4 * TILEF * 4)

template<int RELU>
__global__ void __launch_bounds__(128, 2) gemm_tf32(const float* __restrict__ A,
                                                    const float* __restrict__ W,
                                                    const float* __restrict__ bias,
                                                    float* __restrict__ C,
                                                    int M, int N, int K)
{
    extern __shared__ float smf[];
    const int tid  = threadIdx.x;
    const int wid  = tid >> 5;
    const int lane = tid & 31;
    const int g = lane >> 2;
    const int t = lane & 3;
    const int wm = wid >> 1;
    const int wn = wid & 1;
    const int bm0 = blockIdx.y * 128;
    const int bn0 = blockIdx.x * 128;

    float acc[4][8][4];
#pragma unroll
    for (int mi = 0; mi < 4; mi++)
#pragma unroll
        for (int ni = 0; ni < 8; ni++)
#pragma unroll
            for (int q = 0; q < 4; q++) acc[mi][ni][q] = 0.f;

    int lrow[8], lkc[8];
#pragma unroll
    for (int i = 0; i < 8; i++) {
        int c = tid + i * 128;
        lrow[i] = c >> 3;
        lkc[i]  = (c & 7) << 2;
    }

    const int NS = K / BKG;

    auto issue = [&](int kt, int buf) {
        const int k0 = kt * BKG;
        float* ab = smf + buf * 2 * TILEF;
        float* bb = ab + TILEF;
#pragma unroll
        for (int i = 0; i < 8; i++) {
            uint32_t da = (uint32_t)__cvta_generic_to_shared(&ab[lrow[i] * SST + lkc[i]]);
            const float* ga = A + (size_t)(bm0 + lrow[i]) * K + k0 + lkc[i];
            asm volatile("cp.async.cg.shared.global [%0], [%1], 16;" :: "r"(da), "l"(ga));
        }
#pragma unroll
        for (int i = 0; i < 8; i++) {
            uint32_t db = (uint32_t)__cvta_generic_to_shared(&bb[lrow[i] * SST + lkc[i]]);
            const float* gb = W + (size_t)(bn0 + lrow[i]) * K + k0 + lkc[i];
            asm volatile("cp.async.cg.shared.global [%0], [%1], 16;" :: "r"(db), "l"(gb));
        }
        asm volatile("cp.async.commit_group;");
    };

    issue(0, 0);

    for (int kt = 0; kt < NS; kt++) {
        const int buf = kt & 1;
        if (kt + 1 < NS) {
            issue(kt + 1, buf ^ 1);
            asm volatile("cp.async.wait_group 1;");
        } else {
            asm volatile("cp.async.wait_group 0;");
        }
        __syncthreads();

        const uint32_t* Au = (const uint32_t*)(smf + buf * 2 * TILEF);
        const uint32_t* Bu = Au + TILEF;

#pragma unroll
        for (int ks = 0; ks < 4; ks++) {
            const int k0 = ks * 8;
            uint32_t af[4][4], bf[8][2];
#pragma unroll
            for (int mi = 0; mi < 4; mi++) {
                int r = wm * 64 + mi * 16 + g;
                af[mi][0] = Au[r * SST + k0 + t];
                af[mi][1] = Au[(r + 8) * SST + k0 + t];
                af[mi][2] = Au[r * SST + k0 + 4 + t];
                af[mi][3] = Au[(r + 8) * SST + k0 + 4 + t];
            }
#pragma unroll
            for (int ni = 0; ni < 8; ni++) {
                int n = wn * 64 + ni * 8 + g;
                bf[ni][0] = Bu[n * SST + k0 + t];
                bf[ni][1] = Bu[n * SST + k0 + 4 + t];
            }
#pragma unroll
            for (int mi = 0; mi < 4; mi++)
#pragma unroll
                for (int ni = 0; ni < 8; ni++)
                    mma_tf32(acc[mi][ni], af[mi], bf[ni]);
        }
        __syncthreads();
    }

#pragma unroll
    for (int mi = 0; mi < 4; mi++) {
        int r0 = bm0 + wm * 64 + mi * 16 + g;
#pragma unroll
        for (int ni = 0; ni < 8; ni++) {
            int col = bn0 + wn * 64 + ni * 8 + 2 * t;
            float2 bb = *(const float2*)&bias[col];
            float2 v0, v1;
            v0.x = acc[mi][ni][0] + bb.x; v0.y = acc[mi][ni][1] + bb.y;
            v1.x = acc[mi][ni][2] + bb.x; v1.y = acc[mi][ni][3] + bb.y;
            if (RELU) {
                v0.x = fmaxf(v0.x, 0.f); v0.y = fmaxf(v0.y, 0.f);
                v1.x = fmaxf(v1.x, 0.f); v1.y = fmaxf(v1.y, 0.f);
            }
            *(float2*)&C[(size_t)r0 * N + col] = v0;
            *(float2*)&C[(size_t)(r0 + 8) * N + col] = v1;
        }
    }
}

// ---------------- banded flash attention, tensor-core version ----------------
// Block = (b, h, 64-query tile). 256 threads = 8 warps in 4(m) x 2(n).
// S = Q K^T and O += P V via mma.sync tf32; online softmax in C-frag registers.
// Smem (floats, stride 72): Qs[64], KPs[64] (K then P), Vt[64] (V^T), red bufs.
#define AST 72
#define A_QS   0
#define A_KPS  (64 * AST)
#define A_VT   (128 * AST)
#define A_REDM (192 * AST)            /* 2 x 64 floats */
#define A_REDS (192 * AST + 128)      /* 2 x 64 floats */
#define ATT_SMEM ((192 * AST + 256) * 4)   /* 56320 B */

__global__ void __launch_bounds__(256, 2) attn_banded(const float* __restrict__ qkv,
                                                      float* __restrict__ out,
                                                      const int* __restrict__ winp)
{
    extern __shared__ float sm[];
    float* Qs  = sm + A_QS;
    float* KPs = sm + A_KPS;
    float* Vt  = sm + A_VT;
    float* redM = sm + A_REDM;
    float* redS = sm + A_REDS;

    const int tid  = threadIdx.x;
    const int wid  = tid >> 5;
    const int lane = tid & 31;
    const int g = lane >> 2;
    const int t = lane & 3;
    const int wm = wid >> 1;        // 0..3 : 16-row group
    const int wn = wid & 1;         // 0..1 : 32-col half

    const int nqt = SEQ / 64;
    const int qt = blockIdx.x % nqt;
    const int h  = (blockIdx.x / nqt) % NH;
    const int b  = blockIdx.x / (nqt * NH);
    const int q0 = qt * 64;

    int wraw = *winp;
    int window = (wraw > 0 && wraw < (1 << 20)) ? wraw : (int)__int_as_float(wraw);

    const float scale = 0.125f;  // 1/sqrt(64)

    // load Q tile (scaled + tf32-rounded)
#pragma unroll
    for (int i = 0; i < 4; i++) {
        int idx = i * 256 + tid;
        int r = idx >> 4;
        int c = (idx & 15) << 2;
        float4 v = *(const float4*)&qkv[((size_t)(b * SEQ + q0 + r)) * TD + h * HD + c];
        float4 w;
        w.x = tf32r(v.x * scale); w.y = tf32r(v.y * scale);
        w.z = tf32r(v.z * scale); w.w = tf32r(v.w * scale);
        *(float4*)&Qs[r * AST + c] = w;
    }

    const int m0  = wm * 16;
    const int iq0 = q0 + m0 + g;
    const int iq1 = iq0 + 8;

    float mrow[2] = {-INFINITY, -INFINITY};
    float lrow[2] = {0.f, 0.f};
    float o[4][4];
#pragma unroll
    for (int ni = 0; ni < 4; ni++)
#pragma unroll
        for (int q = 0; q < 4; q++) o[ni][q] = 0.f;

    int kt0 = qt - 2; if (kt0 < 0) kt0 = 0;
    int kt1 = qt + 2; if (kt1 > nqt - 1) kt1 = nqt - 1;

    for (int kt = kt0; kt <= kt1; kt++) {
        const int k0 = kt * 64;
        __syncthreads();   // prior-iter smem reads done (also orders Q store once)

        // K tile row-major (rounded); V tile transposed (rounded)
#pragma unroll
        for (int i = 0; i < 4; i++) {
            int idx = i * 256 + tid;
            int r = idx >> 4;
            int c = (idx & 15) << 2;
            const size_t rowb = (size_t)(b * SEQ + k0 + r) * TD;
            float4 kv = *(const float4*)&qkv[rowb + DIM + h * HD + c];
            float4 kw;
            kw.x = tf32r(kv.x); kw.y = tf32r(kv.y); kw.z = tf32r(kv.z); kw.w = tf32r(kv.w);
            *(float4*)&KPs[r * AST + c] = kw;
            float4 vv = *(const float4*)&qkv[rowb + 2 * DIM + h * HD + c];
            Vt[(c + 0) * AST + r] = tf32r(vv.x);
            Vt[(c + 1) * AST + r] = tf32r(vv.y);
            Vt[(c + 2) * AST + r] = tf32r(vv.z);
            Vt[(c + 3) * AST + r] = tf32r(vv.w);
        }
        __syncthreads();

        // S = Q K^T  (warp tile 16x32, 4 n-tiles of 8)
        float sv[4][4];
#pragma unroll
        for (int ni = 0; ni < 4; ni++)
#pragma unroll
            for (int q = 0; q < 4; q++) sv[ni][q] = 0.f;

        const uint32_t* Qu = (const uint32_t*)Qs;
        const uint32_t* Ku = (const uint32_t*)KPs;
#pragma unroll
        for (int ks = 0; ks < 8; ks++) {
            const int kk = ks * 8;
            uint32_t af[4];
            af[0] = Qu[(m0 + g) * AST + kk + t];
            af[1] = Qu[(m0 + g + 8) * AST + kk + t];
            af[2] = Qu[(m0 + g) * AST + kk + 4 + t];
            af[3] = Qu[(m0 + g + 8) * AST + kk + 4 + t];
#pragma unroll
            for (int ni = 0; ni < 4; ni++) {
                uint32_t bf[2];
                int n = wn * 32 + ni * 8 + g;
                bf[0] = Ku[n * AST + kk + t];
                bf[1] = Ku[n * AST + kk + 4 + t];
                mma_tf32(sv[ni], af, bf);
            }
        }

        // mask + per-thread partial row max
        float pm0 = -INFINITY, pm1 = -INFINITY;
#pragma unroll
        for (int ni = 0; ni < 4; ni++) {
#pragma unroll
            for (int c = 0; c < 2; c++) {
                int j = k0 + wn * 32 + ni * 8 + 2 * t + c;
                int d0 = iq0 - j; d0 = d0 < 0 ? -d0 : d0;
                int d1 = iq1 - j; d1 = d1 < 0 ? -d1 : d1;
                if (d0 > window) sv[ni][c]     = -INFINITY;
                if (d1 > window) sv[ni][2 + c] = -INFINITY;
                pm0 = fmaxf(pm0, sv[ni][c]);
                pm1 = fmaxf(pm1, sv[ni][2 + c]);
            }
        }
        pm0 = fmaxf(pm0, __shfl_xor_sync(0xffffffffu, pm0, 1));
        pm0 = fmaxf(pm0, __shfl_xor_sync(0xffffffffu, pm0, 2));
        pm1 = fmaxf(pm1, __shfl_xor_sync(0xffffffffu, pm1, 1));
        pm1 = fmaxf(pm1, __shfl_xor_sync(0xffffffffu, pm1, 2));
        if (t == 0) {
            redM[wn * 64 + m0 + g]     = pm0;
            redM[wn * 64 + m0 + g + 8] = pm1;
        }
        __syncthreads();   // also: all QK reads of KPs complete -> safe to overwrite with P

        float rmax0 = fmaxf(redM[m0 + g],     redM[64 + m0 + g]);
        float rmax1 = fmaxf(redM[m0 + g + 8], redM[64 + m0 + g + 8]);
        float nm0 = fmaxf(mrow[0], rmax0);
        float nm1 = fmaxf(mrow[1], rmax1);
        float a0 = (nm0 == -INFINITY) ? 1.f : __expf(mrow[0] - nm0);
        float a1 = (nm1 == -INFINITY) ? 1.f : __expf(mrow[1] - nm1);

        float ps0 = 0.f, ps1 = 0.f;
#pragma unroll
        for (int ni = 0; ni < 4; ni++) {
#pragma unroll
            for (int c = 0; c < 2; c++) {
                float p0 = (nm0 == -INFINITY) ? 0.f : __expf(sv[ni][c] - nm0);
                float p1 = (nm1 == -INFINITY) ? 0.f : __expf(sv[ni][2 + c] - nm1);
                ps0 += p0; ps1 += p1;
                KPs[(m0 + g) * AST + wn * 32 + ni * 8 + 2 * t + c]     = tf32r(p0);
                KPs[(m0 + g + 8) * AST + wn * 32 + ni * 8 + 2 * t + c] = tf32r(p1);
            }
        }
        ps0 += __shfl_xor_sync(0xffffffffu, ps0, 1);
        ps0 += __shfl_xor_sync(0xffffffffu, ps0, 2);
        ps1 += __shfl_xor_sync(0xffffffffu, ps1, 1);
        ps1 += __shfl_xor_sync(0xffffffffu, ps1, 2);
        if (t == 0) {
            redS[wn * 64 + m0 + g]     = ps0;
            redS[wn * 64 + m0 + g + 8] = ps1;
        }
        __syncthreads();   // P fully written; sums visible

        float rs0 = redS[m0 + g]     + redS[64 + m0 + g];
        float rs1 = redS[m0 + g + 8] + redS[64 + m0 + g + 8];
        lrow[0] = lrow[0] * a0 + rs0;  mrow[0] = nm0;
        lrow[1] = lrow[1] * a1 + rs1;  mrow[1] = nm1;
#pragma unroll
        for (int ni = 0; ni < 4; ni++) {
            o[ni][0] *= a0; o[ni][1] *= a0;
            o[ni][2] *= a1; o[ni][3] *= a1;
        }

        // O += P V   (A = P rows m0..m0+15 all k; B = Vt[d][k], d split by wn)
        const uint32_t* Pu = (const uint32_t*)KPs;
        const uint32_t* Vu = (const uint32_t*)Vt;
#pragma unroll
        for (int ks = 0; ks < 8; ks++) {
            const int kk = ks * 8;
            uint32_t af[4];
            af[0] = Pu[(m0 + g) * AST + kk + t];
            af[1] = Pu[(m0 + g + 8) * AST + kk + t];
            af[2] = Pu[(m0 + g) * AST + kk + 4 + t];
            af[3] = Pu[(m0 + g + 8) * AST + kk + 4 + t];
#pragma unroll
            for (int ni = 0; ni < 4; ni++) {
                uint32_t bf[2];
                int n = wn * 32 + ni * 8 + g;
                bf[0] = Vu[n * AST + kk + t];
                bf[1] = Vu[n * AST + kk + 4 + t];
                mma_tf32(o[ni], af, bf);
            }
        }
    }

    // normalize + write
    float inv0 = 1.f / lrow[0];
    float inv1 = 1.f / lrow[1];
#pragma unroll
    for (int ni = 0; ni < 4; ni++) {
        int col = h * HD + wn * 32 + ni * 8 + 2 * t;
        float2 v0, v1;
        v0.x = o[ni][0] * inv0; v0.y = o[ni][1] * inv0;
        v1.x = o[ni][2] * inv1; v1.y = o[ni][3] * inv1;
        *(float2*)&out[(size_t)(b * SEQ + iq0) * DIM + col] = v0;
        *(float2*)&out[(size_t)(b * SEQ + iq1) * DIM + col] = v1;
    }
}

// ---------------- fused residual-add + LayerNorm -------------
__global__ void __launch_bounds__(256) add_ln_kernel(const float* __restrict__ X,
                                                     const float* __restrict__ Y,
                                                     const float* __restrict__ g,
                                                     const float* __restrict__ bt,
                                                     float* __restrict__ out)
{
    const int row = blockIdx.x;
    const int tid = threadIdx.x;
    const size_t base = (size_t)row * DIM + tid * 4;

    float4 xv = *(const float4*)&X[base];
    float4 yv = *(const float4*)&Y[base];
    float v0 = xv.x + yv.x, v1 = xv.y + yv.y, v2 = xv.z + yv.z, v3 = xv.w + yv.w;

    float s  = v0 + v1 + v2 + v3;
    float sq = v0 * v0 + v1 * v1 + v2 * v2 + v3 * v3;
#pragma unroll
    for (int off = 16; off; off >>= 1) {
        s  += __shfl_xor_sync(0xffffffffu, s, off);
        sq += __shfl_xor_sync(0xffffffffu, sq, off);
    }
    __shared__ float ss[8], sqs[8];
    __shared__ float mu_s, ri_s;
    int w = tid >> 5;
    if ((tid & 31) == 0) { ss[w] = s; sqs[w] = sq; }
    __syncthreads();
    if (tid == 0) {
        float St = 0.f, Qt = 0.f;
#pragma unroll
        for (int i = 0; i < 8; i++) { St += ss[i]; Qt += sqs[i]; }
        float mu = St * (1.f / DIM);
        float var = Qt * (1.f / DIM) - mu * mu;
        mu_s = mu;
        ri_s = rsqrtf(var + 1e-5f);
    }
    __syncthreads();
    float mu = mu_s, ri = ri_s;

    float4 gg = *(const float4*)&g[tid * 4];
    float4 bb = *(const float4*)&bt[tid * 4];
    float4 r;
    r.x = (v0 - mu) * ri * gg.x + bb.x;
    r.y = (v1 - mu) * ri * gg.y + bb.y;
    r.z = (v2 - mu) * ri * gg.z + bb.z;
    r.w = (v3 - mu) * ri * gg.w + bb.w;
    *(float4*)&out[base] = r;
}

// ---------------- launch ----------------
extern "C" void kernel_launch(void* const* d_in, const int* in_sizes, int n_in,
                              void* d_out, int out_size)
{
    const float* x    = (const float*)d_in[0];
    const float* inw  = (const float*)d_in[1];
    const float* inb  = (const float*)d_in[2];
    const float* ow   = (const float*)d_in[3];
    const float* ob   = (const float*)d_in[4];
    const float* l1g  = (const float*)d_in[5];
    const float* l1b  = (const float*)d_in[6];
    const float* w1   = (const float*)d_in[7];
    const float* b1   = (const float*)d_in[8];
    const float* w2   = (const float*)d_in[9];
    const float* b2   = (const float*)d_in[10];
    const float* l2g  = (const float*)d_in[11];
    const float* l2b  = (const float*)d_in[12];
    const int*   win  = (const int*)d_in[13];
    float* out = (float*)d_out;

    float *qkv, *attn, *attnout, *x2, *hbuf, *ffb;
    cudaGetSymbolAddress((void**)&qkv,     g_qkv);
    cudaGetSymbolAddress((void**)&attn,    g_attn);
    cudaGetSymbolAddress((void**)&attnout, g_attnout);
    cudaGetSymbolAddress((void**)&x2,      g_x2);
    cudaGetSymbolAddress((void**)&hbuf,    g_h);
    cudaGetSymbolAddress((void**)&ffb,     g_ff);

    cudaFuncSetAttribute(gemm_tf32<0>, cudaFuncAttributeMaxDynamicSharedMemorySize, GSMEM_BYTES);
    cudaFuncSetAttribute(gemm_tf32<1>, cudaFuncAttributeMaxDynamicSharedMemorySize, GSMEM_BYTES);
    cudaFuncSetAttribute(attn_banded,  cudaFuncAttributeMaxDynamicSharedMemorySize, ATT_SMEM);

    dim3 gblk(128);
    dim3 blk(256);

    // 1) QKV projection
    gemm_tf32<0><<<dim3(TD / 128, MR / 128), gblk, GSMEM_BYTES>>>(x, inw, inb, qkv, MR, TD, DIM);
    // 2) banded attention (tensor cores)
    attn_banded<<<BATCH * NH * (SEQ / 64), blk, ATT_SMEM>>>(qkv, attn, win);
    // 3) out projection
    gemm_tf32<0><<<dim3(DIM / 128, MR / 128), gblk, GSMEM_BYTES>>>(attn, ow, ob, attnout, MR, DIM, DIM);
    // 4) x2 = LN1(x + attn_out)
    add_ln_kernel<<<MR, blk>>>(x, attnout, l1g, l1b, x2);
    // 5) h = relu(x2 @ w1^T + b1)
    gemm_tf32<1><<<dim3(DFF / 128, MR / 128), gblk, GSMEM_BYTES>>>(x2, w1, b1, hbuf, MR, DFF, DIM);
    // 6) ff = h @ w2^T + b2
    gemm_tf32<0><<<dim3(DIM / 128, MR / 128), gblk, GSMEM_BYTES>>>(hbuf, w2, b2, ffb, MR, DIM, DFF);
    // 7) out = LN2(x2 + ff)
    add_ln_kernel<<<MR, blk>>>(x2, ffb, l2g, l2b, out);
}

// round 13
// speedup vs baseline: 3.7757x; 1.0412x over previous
#include <cuda_runtime.h>
#include <cuda_fp16.h>
#include <math.h>
#include <stdint.h>

#define BATCH 2
#define SEQ   2048
#define DIM   1024
#define NH    16
#define HD    64
#define DFF   4096
#define MR    (BATCH*SEQ)     /* 4096 rows */
#define TD    (3*DIM)         /* 3072 */

// ---------------- scratch (static device globals; no allocation) ----------------
__device__ __half g_qkvh[MR * TD];
__device__ __half g_attnh[MR * DIM];
__device__ float  g_attnout[MR * DIM];
__device__ float  g_x2[MR * DIM];
__device__ __half g_x2h[MR * DIM];
__device__ __half g_hh[MR * DFF];
__device__ float  g_ff[MR * DIM];
__device__ __half g_xh[MR * DIM];
__device__ __half g_wih[TD * DIM];
__device__ __half g_woh[DIM * DIM];
__device__ __half g_w1h[DFF * DIM];
__device__ __half g_w2h[DIM * DFF];

__device__ __forceinline__ uint32_t f2tf(float x) {
    uint32_t r;
    asm("cvt.rna.tf32.f32 %0, %1;" : "=r"(r) : "f"(x));
    return r;
}
__device__ __forceinline__ float tf32r(float x) { return __uint_as_float(f2tf(x)); }

__device__ __forceinline__ void mma_tf32(float* c, const uint32_t* a, const uint32_t* b) {
    asm volatile(
        "mma.sync.aligned.m16n8k8.row.col.f32.tf32.tf32.f32 "
        "{%0,%1,%2,%3}, {%4,%5,%6,%7}, {%8,%9}, {%0,%1,%2,%3};"
        : "+f"(c[0]), "+f"(c[1]), "+f"(c[2]), "+f"(c[3])
        : "r"(a[0]), "r"(a[1]), "r"(a[2]), "r"(a[3]), "r"(b[0]), "r"(b[1]));
}

__device__ __forceinline__ void mma_f16(float* c, const uint32_t* a, const uint32_t* b) {
    asm volatile(
        "mma.sync.aligned.m16n8k16.row.col.f32.f16.f16.f32 "
        "{%0,%1,%2,%3}, {%4,%5,%6,%7}, {%8,%9}, {%0,%1,%2,%3};"
        : "+f"(c[0]), "+f"(c[1]), "+f"(c[2]), "+f"(c[3])
        : "r"(a[0]), "r"(a[1]), "r"(a[2]), "r"(a[3]), "r"(b[0]), "r"(b[1]));
}

// ---------------- fp32 -> fp16 conversion (n divisible by 1024) --------------
__global__ void __launch_bounds__(256) f2h_kernel(const float* __restrict__ src,
                                                  __half* __restrict__ dst)
{
    int i = (blockIdx.x * 256 + threadIdx.x) * 4;
    float4 v = *(const float4*)&src[i];
    __half2 h0 = __floats2half2_rn(v.x, v.y);
    __half2 h1 = __floats2half2_rn(v.z, v.w);
    *(__half2*)&dst[i]     = h0;
    *(__half2*)&dst[i + 2] = h1;
}

// ---------------- FP16 tensor-core GEMM --------------------------------------
// C[M,N] = A[M,K] @ W[N,K]^T + bias (opt ReLU). A,W fp16; accum fp32.
// 128x128 block tile, BK=64 fp16 (128 B/row), 128 threads (4 warps 2x2),
// warp tile 64x64, mma m16n8k16. smem row stride 36 words (72 fp16):
// bank = (4g+t) mod 32 -> conflict-free fragment reads.
#define BKH   64
#define SSTH  36                       /* words per smem row */
#define TILEW (128 * SSTH)             /* words per tile */
#define GSMEM_BYTES (4 * TILEW * 4)    /* 2 bufs x (A+B) = 73728 B */

template<int RELU, int OUTH>
__global__ void __launch_bounds__(128, 2) gemm_f16(const __half* __restrict__ A,
                                                   const __half* __restrict__ W,
                                                   const float* __restrict__ bias,
                                                   void* __restrict__ Cout,
                                                   int M, int N, int K)
{
    extern __shared__ uint32_t smw[];
    const int tid  = threadIdx.x;
    const int wid  = tid >> 5;
    const int lane = tid & 31;
    const int g = lane >> 2;
    const int t = lane & 3;
    const int wm = wid >> 1;
    const int wn = wid & 1;
    const int bm0 = blockIdx.y * 128;
    const int bn0 = blockIdx.x * 128;

    float acc[4][8][4];
#pragma unroll
    for (int mi = 0; mi < 4; mi++)
#pragma unroll
        for (int ni = 0; ni < 8; ni++)
#pragma unroll
            for (int q = 0; q < 4; q++) acc[mi][ni][q] = 0.f;

    // per thread: 8 chunks (16B = 8 fp16) of A + 8 of B per stage
    int lrow[8], lkc[8];
#pragma unroll
    for (int i = 0; i < 8; i++) {
        int c = tid + i * 128;        // 0..1023
        lrow[i] = c >> 3;             // 0..127
        lkc[i]  = c & 7;              // chunk of 8 fp16
    }

    const int NS = K / BKH;

    auto issue = [&](int kt, int buf) {
        const int k0 = kt * BKH;
        uint32_t* ab = smw + buf * 2 * TILEW;
        uint32_t* bb = ab + TILEW;
#pragma unroll
        for (int i = 0; i < 8; i++) {
            uint32_t da = (uint32_t)__cvta_generic_to_shared(&ab[lrow[i] * SSTH + lkc[i] * 4]);
            const __half* ga = A + (size_t)(bm0 + lrow[i]) * K + k0 + lkc[i] * 8;
            asm volatile("cp.async.cg.shared.global [%0], [%1], 16;" :: "r"(da), "l"(ga));
        }
#pragma unroll
        for (int i = 0; i < 8; i++) {
            uint32_t db = (uint32_t)__cvta_generic_to_shared(&bb[lrow[i] * SSTH + lkc[i] * 4]);
            const __half* gb = W + (size_t)(bn0 + lrow[i]) * K + k0 + lkc[i] * 8;
            asm volatile("cp.async.cg.shared.global [%0], [%1], 16;" :: "r"(db), "l"(gb));
        }
        asm volatile("cp.async.commit_group;");
    };

    issue(0, 0);

    for (int kt = 0; kt < NS; kt++) {
        const int buf = kt & 1;
        if (kt + 1 < NS) {
            issue(kt + 1, buf ^ 1);
            asm volatile("cp.async.wait_group 1;");
        } else {
            asm volatile("cp.async.wait_group 0;");
        }
        __syncthreads();

        const uint32_t* Au = smw + buf * 2 * TILEW;
        const uint32_t* Bu = Au + TILEW;

#pragma unroll
        for (int ks = 0; ks < 4; ks++) {
            const int kw = ks * 8;          // word offset of this k16 slice
            uint32_t af[4][4], bf[8][2];
#pragma unroll
            for (int mi = 0; mi < 4; mi++) {
                int r = wm * 64 + mi * 16 + g;
                af[mi][0] = Au[r * SSTH + kw + t];
                af[mi][1] = Au[(r + 8) * SSTH + kw + t];
                af[mi][2] = Au[r * SSTH + kw + 4 + t];
                af[mi][3] = Au[(r + 8) * SSTH + kw + 4 + t];
            }
#pragma unroll
            for (int ni = 0; ni < 8; ni++) {
                int n = wn * 64 + ni * 8 + g;
                bf[ni][0] = Bu[n * SSTH + kw + t];
                bf[ni][1] = Bu[n * SSTH + kw + 4 + t];
            }
#pragma unroll
            for (int mi = 0; mi < 4; mi++)
#pragma unroll
                for (int ni = 0; ni < 8; ni++)
                    mma_f16(acc[mi][ni], af[mi], bf[ni]);
        }
        __syncthreads();
    }

    // epilogue: bias (+relu), store fp32 or fp16
#pragma unroll
    for (int mi = 0; mi < 4; mi++) {
        int r0 = bm0 + wm * 64 + mi * 16 + g;
#pragma unroll
        for (int ni = 0; ni < 8; ni++) {
            int col = bn0 + wn * 64 + ni * 8 + 2 * t;
            float2 bb = *(const float2*)&bias[col];
            float2 v0, v1;
            v0.x = acc[mi][ni][0] + bb.x; v0.y = acc[mi][ni][1] + bb.y;
            v1.x = acc[mi][ni][2] + bb.x; v1.y = acc[mi][ni][3] + bb.y;
            if (RELU) {
                v0.x = fmaxf(v0.x, 0.f); v0.y = fmaxf(v0.y, 0.f);
                v1.x = fmaxf(v1.x, 0.f); v1.y = fmaxf(v1.y, 0.f);
            }
            if (OUTH) {
                __half* C = (__half*)Cout;
                *(__half2*)&C[(size_t)r0 * N + col]       = __floats2half2_rn(v0.x, v0.y);
                *(__half2*)&C[(size_t)(r0 + 8) * N + col] = __floats2half2_rn(v1.x, v1.y);
            } else {
                float* C = (float*)Cout;
                *(float2*)&C[(size_t)r0 * N + col]       = v0;
                *(float2*)&C[(size_t)(r0 + 8) * N + col] = v1;
            }
        }
    }
}

// ---------------- banded flash attention, tensor-core (fp16 in/out) ----------
// Block = (b, h, 64-query tile). 256 threads = 8 warps in 4(m) x 2(n).
// S = Q K^T and O += P V via mma.sync tf32 (fp16-sourced values are exact in
// tf32); online softmax in C-frag registers.
#define AST 72
#define A_QS   0
#define A_KPS  (64 * AST)
#define A_VT   (128 * AST)
#define A_REDM (192 * AST)
#define A_REDS (192 * AST + 128)
#define ATT_SMEM ((192 * AST + 256) * 4)

__global__ void __launch_bounds__(256, 2) attn_banded(const __half* __restrict__ qkv,
                                                      __half* __restrict__ out,
                                                      const int* __restrict__ winp)
{
    extern __shared__ float sm[];
    float* Qs  = sm + A_QS;
    float* KPs = sm + A_KPS;
    float* Vt  = sm + A_VT;
    float* redM = sm + A_REDM;
    float* redS = sm + A_REDS;

    const int tid  = threadIdx.x;
    const int wid  = tid >> 5;
    const int lane = tid & 31;
    const int g = lane >> 2;
    const int t = lane & 3;
    const int wm = wid >> 1;
    const int wn = wid & 1;

    const int nqt = SEQ / 64;
    const int qt = blockIdx.x % nqt;
    const int h  = (blockIdx.x / nqt) % NH;
    const int b  = blockIdx.x / (nqt * NH);
    const int q0 = qt * 64;

    int wraw = *winp;
    int window = (wraw > 0 && wraw < (1 << 20)) ? wraw : (int)__int_as_float(wraw);

    const float scale = 0.125f;

    // load Q tile (fp16 -> fp32, scaled; exact in tf32)
#pragma unroll
    for (int i = 0; i < 4; i++) {
        int idx = i * 256 + tid;
        int r = idx >> 4;
        int c = (idx & 15) << 2;
        uint2 raw = *(const uint2*)&qkv[(size_t)(b * SEQ + q0 + r) * TD + h * HD + c];
        float2 f0 = __half22float2(*(__half2*)&raw.x);
        float2 f1 = __half22float2(*(__half2*)&raw.y);
        Qs[r * AST + c + 0] = f0.x * scale; Qs[r * AST + c + 1] = f0.y * scale;
        Qs[r * AST + c + 2] = f1.x * scale; Qs[r * AST + c + 3] = f1.y * scale;
    }

    const int m0  = wm * 16;
    const int iq0 = q0 + m0 + g;
    const int iq1 = iq0 + 8;

    float mrow[2] = {-INFINITY, -INFINITY};
    float lrow[2] = {0.f, 0.f};
    float o[4][4];
#pragma unroll
    for (int ni = 0; ni < 4; ni++)
#pragma unroll
        for (int q = 0; q < 4; q++) o[ni][q] = 0.f;

    int kt0 = qt - 2; if (kt0 < 0) kt0 = 0;
    int kt1 = qt + 2; if (kt1 > nqt - 1) kt1 = nqt - 1;

    for (int kt = kt0; kt <= kt1; kt++) {
        const int k0 = kt * 64;
        __syncthreads();

#pragma unroll
        for (int i = 0; i < 4; i++) {
            int idx = i * 256 + tid;
            int r = idx >> 4;
            int c = (idx & 15) << 2;
            const size_t rowb = (size_t)(b * SEQ + k0 + r) * TD;
            uint2 kraw = *(const uint2*)&qkv[rowb + DIM + h * HD + c];
            float2 k0f = __half22float2(*(__half2*)&kraw.x);
            float2 k1f = __half22float2(*(__half2*)&kraw.y);
            KPs[r * AST + c + 0] = k0f.x; KPs[r * AST + c + 1] = k0f.y;
            KPs[r * AST + c + 2] = k1f.x; KPs[r * AST + c + 3] = k1f.y;
            uint2 vraw = *(const uint2*)&qkv[rowb + 2 * DIM + h * HD + c];
            float2 v0f = __half22float2(*(__half2*)&vraw.x);
            float2 v1f = __half22float2(*(__half2*)&vraw.y);
            Vt[(c + 0) * AST + r] = v0f.x;
            Vt[(c + 1) * AST + r] = v0f.y;
            Vt[(c + 2) * AST + r] = v1f.x;
            Vt[(c + 3) * AST + r] = v1f.y;
        }
        __syncthreads();

        // S = Q K^T
        float sv[4][4];
#pragma unroll
        for (int ni = 0; ni < 4; ni++)
#pragma unroll
            for (int q = 0; q < 4; q++) sv[ni][q] = 0.f;

        const uint32_t* Qu = (const uint32_t*)Qs;
        const uint32_t* Ku = (const uint32_t*)KPs;
#pragma unroll
        for (int ks = 0; ks < 8; ks++) {
            const int kk = ks * 8;
            uint32_t af[4];
            af[0] = Qu[(m0 + g) * AST + kk + t];
            af[1] = Qu[(m0 + g + 8) * AST + kk + t];
            af[2] = Qu[(m0 + g) * AST + kk + 4 + t];
            af[3] = Qu[(m0 + g + 8) * AST + kk + 4 + t];
#pragma unroll
            for (int ni = 0; ni < 4; ni++) {
                uint32_t bf[2];
                int n = wn * 32 + ni * 8 + g;
                bf[0] = Ku[n * AST + kk + t];
                bf[1] = Ku[n * AST + kk + 4 + t];
                mma_tf32(sv[ni], af, bf);
            }
        }

        // mask + partial row max
        float pm0 = -INFINITY, pm1 = -INFINITY;
#pragma unroll
        for (int ni = 0; ni < 4; ni++) {
#pragma unroll
            for (int c = 0; c < 2; c++) {
                int j = k0 + wn * 32 + ni * 8 + 2 * t + c;
                int d0 = iq0 - j; d0 = d0 < 0 ? -d0 : d0;
                int d1 = iq1 - j; d1 = d1 < 0 ? -d1 : d1;
                if (d0 > window) sv[ni][c]     = -INFINITY;
                if (d1 > window) sv[ni][2 + c] = -INFINITY;
                pm0 = fmaxf(pm0, sv[ni][c]);
                pm1 = fmaxf(pm1, sv[ni][2 + c]);
            }
        }
        pm0 = fmaxf(pm0, __shfl_xor_sync(0xffffffffu, pm0, 1));
        pm0 = fmaxf(pm0, __shfl_xor_sync(0xffffffffu, pm0, 2));
        pm1 = fmaxf(pm1, __shfl_xor_sync(0xffffffffu, pm1, 1));
        pm1 = fmaxf(pm1, __shfl_xor_sync(0xffffffffu, pm1, 2));
        if (t == 0) {
            redM[wn * 64 + m0 + g]     = pm0;
            redM[wn * 64 + m0 + g + 8] = pm1;
        }
        __syncthreads();

        float rmax0 = fmaxf(redM[m0 + g],     redM[64 + m0 + g]);
        float rmax1 = fmaxf(redM[m0 + g + 8], redM[64 + m0 + g + 8]);
        float nm0 = fmaxf(mrow[0], rmax0);
        float nm1 = fmaxf(mrow[1], rmax1);
        float a0 = (nm0 == -INFINITY) ? 1.f : __expf(mrow[0] - nm0);
        float a1 = (nm1 == -INFINITY) ? 1.f : __expf(mrow[1] - nm1);

        float ps0 = 0.f, ps1 = 0.f;
#pragma unroll
        for (int ni = 0; ni < 4; ni++) {
#pragma unroll
            for (int c = 0; c < 2; c++) {
                float p0 = (nm0 == -INFINITY) ? 0.f : __expf(sv[ni][c] - nm0);
                float p1 = (nm1 == -INFINITY) ? 0.f : __expf(sv[ni][2 + c] - nm1);
                ps0 += p0; ps1 += p1;
                KPs[(m0 + g) * AST + wn * 32 + ni * 8 + 2 * t + c]     = tf32r(p0);
                KPs[(m0 + g + 8) * AST + wn * 32 + ni * 8 + 2 * t + c] = tf32r(p1);
            }
        }
        ps0 += __shfl_xor_sync(0xffffffffu, ps0, 1);
        ps0 += __shfl_xor_sync(0xffffffffu, ps0, 2);
        ps1 += __shfl_xor_sync(0xffffffffu, ps1, 1);
        ps1 += __shfl_xor_sync(0xffffffffu, ps1, 2);
        if (t == 0) {
            redS[wn * 64 + m0 + g]     = ps0;
            redS[wn * 64 + m0 + g + 8] = ps1;
        }
        __syncthreads();

        float rs0 = redS[m0 + g]     + redS[64 + m0 + g];
        float rs1 = redS[m0 + g + 8] + redS[64 + m0 + g + 8];
        lrow[0] = lrow[0] * a0 + rs0;  mrow[0] = nm0;
        lrow[1] = lrow[1] * a1 + rs1;  mrow[1] = nm1;
#pragma unroll
        for (int ni = 0; ni < 4; ni++) {
            o[ni][0] *= a0; o[ni][1] *= a0;
            o[ni][2] *= a1; o[ni][3] *= a1;
        }

        // O += P V
        const uint32_t* Pu = (const uint32_t*)KPs;
        const uint32_t* Vu = (const uint32_t*)Vt;
#pragma unroll
        for (int ks = 0; ks < 8; ks++) {
            const int kk = ks * 8;
            uint32_t af[4];
            af[0] = Pu[(m0 + g) * AST + kk + t];
            af[1] = Pu[(m0 + g + 8) * AST + kk + t];
            af[2] = Pu[(m0 + g) * AST + kk + 4 + t];
            af[3] = Pu[(m0 + g + 8) * AST + kk + 4 + t];
#pragma unroll
            for (int ni = 0; ni < 4; ni++) {
                uint32_t bf[2];
                int n = wn * 32 + ni * 8 + g;
                bf[0] = Vu[n * AST + kk + t];
                bf[1] = Vu[n * AST + kk + 4 + t];
                mma_tf32(o[ni], af, bf);
            }
        }
    }

    // normalize + write fp16
    float inv0 = 1.f / lrow[0];
    float inv1 = 1.f / lrow[1];
#pragma unroll
    for (int ni = 0; ni < 4; ni++) {
        int col = h * HD + wn * 32 + ni * 8 + 2 * t;
        *(__half2*)&out[(size_t)(b * SEQ + iq0) * DIM + col] =
            __floats2half2_rn(o[ni][0] * inv0, o[ni][1] * inv0);
        *(__half2*)&out[(size_t)(b * SEQ + iq1) * DIM + col] =
            __floats2half2_rn(o[ni][2] * inv1, o[ni][3] * inv1);
    }
}

// ---------------- fused residual-add + LayerNorm (dual fp32/fp16 out) --------
__global__ void __launch_bounds__(256) add_ln_kernel(const float* __restrict__ X,
                                                     const float* __restrict__ Y,
                                                     const float* __restrict__ g,
                                                     const float* __restrict__ bt,
                                                     float* __restrict__ out,
                                                     __half* __restrict__ outh)
{
    const int row = blockIdx.x;
    const int tid = threadIdx.x;
    const size_t base = (size_t)row * DIM + tid * 4;

    float4 xv = *(const float4*)&X[base];
    float4 yv = *(const float4*)&Y[base];
    float v0 = xv.x + yv.x, v1 = xv.y + yv.y, v2 = xv.z + yv.z, v3 = xv.w + yv.w;

    float s  = v0 + v1 + v2 + v3;
    float sq = v0 * v0 + v1 * v1 + v2 * v2 + v3 * v3;
#pragma unroll
    for (int off = 16; off; off >>= 1) {
        s  += __shfl_xor_sync(0xffffffffu, s, off);
        sq += __shfl_xor_sync(0xffffffffu, sq, off);
    }
    __shared__ float ss[8], sqs[8];
    __shared__ float mu_s, ri_s;
    int w = tid >> 5;
    if ((tid & 31) == 0) { ss[w] = s; sqs[w] = sq; }
    __syncthreads();
    if (tid == 0) {
        float St = 0.f, Qt = 0.f;
#pragma unroll
        for (int i = 0; i < 8; i++) { St += ss[i]; Qt += sqs[i]; }
        float mu = St * (1.f / DIM);
        float var = Qt * (1.f / DIM) - mu * mu;
        mu_s = mu;
        ri_s = rsqrtf(var + 1e-5f);
    }
    __syncthreads();
    float mu = mu_s, ri = ri_s;

    float4 gg = *(const float4*)&g[tid * 4];
    float4 bb = *(const float4*)&bt[tid * 4];
    float4 r;
    r.x = (v0 - mu) * ri * gg.x + bb.x;
    r.y = (v1 - mu) * ri * gg.y + bb.y;
    r.z = (v2 - mu) * ri * gg.z + bb.z;
    r.w = (v3 - mu) * ri * gg.w + bb.w;
    *(float4*)&out[base] = r;
    if (outh) {
        *(__half2*)&outh[base]     = __floats2half2_rn(r.x, r.y);
        *(__half2*)&outh[base + 2] = __floats2half2_rn(r.z, r.w);
    }
}

// ---------------- launch ----------------
extern "C" void kernel_launch(void* const* d_in, const int* in_sizes, int n_in,
                              void* d_out, int out_size)
{
    const float* x    = (const float*)d_in[0];
    const float* inw  = (const float*)d_in[1];
    const float* inb  = (const float*)d_in[2];
    const float* ow   = (const float*)d_in[3];
    const float* ob   = (const float*)d_in[4];
    const float* l1g  = (const float*)d_in[5];
    const float* l1b  = (const float*)d_in[6];
    const float* w1   = (const float*)d_in[7];
    const float* b1   = (const float*)d_in[8];
    const float* w2   = (const float*)d_in[9];
    const float* b2   = (const float*)d_in[10];
    const float* l2g  = (const float*)d_in[11];
    const float* l2b  = (const float*)d_in[12];
    const int*   win  = (const int*)d_in[13];
    float* out = (float*)d_out;

    __half *qkvh, *attnh, *x2h, *hh, *xh, *wih, *woh, *w1h, *w2h;
    float *attnout, *x2, *ffb;
    cudaGetSymbolAddress((void**)&qkvh,    g_qkvh);
    cudaGetSymbolAddress((void**)&attnh,   g_attnh);
    cudaGetSymbolAddress((void**)&attnout, g_attnout);
    cudaGetSymbolAddress((void**)&x2,      g_x2);
    cudaGetSymbolAddress((void**)&x2h,     g_x2h);
    cudaGetSymbolAddress((void**)&hh,      g_hh);
    cudaGetSymbolAddress((void**)&ffb,     g_ff);
    cudaGetSymbolAddress((void**)&xh,      g_xh);
    cudaGetSymbolAddress((void**)&wih,     g_wih);
    cudaGetSymbolAddress((void**)&woh,     g_woh);
    cudaGetSymbolAddress((void**)&w1h,     g_w1h);
    cudaGetSymbolAddress((void**)&w2h,     g_w2h);

    cudaFuncSetAttribute(gemm_f16<0,0>, cudaFuncAttributeMaxDynamicSharedMemorySize, GSMEM_BYTES);
    cudaFuncSetAttribute(gemm_f16<0,1>, cudaFuncAttributeMaxDynamicSharedMemorySize, GSMEM_BYTES);
    cudaFuncSetAttribute(gemm_f16<1,1>, cudaFuncAttributeMaxDynamicSharedMemorySize, GSMEM_BYTES);
    cudaFuncSetAttribute(attn_banded,   cudaFuncAttributeMaxDynamicSharedMemorySize, ATT_SMEM);

    dim3 gblk(128);
    dim3 blk(256);

    // 0) fp32 -> fp16 copies of x and weights
    f2h_kernel<<<(MR * DIM) / 1024, 256>>>(x,   xh);
    f2h_kernel<<<(TD * DIM) / 1024, 256>>>(inw, wih);
    f2h_kernel<<<(DIM * DIM) / 1024, 256>>>(ow, woh);
    f2h_kernel<<<(DFF * DIM) / 1024, 256>>>(w1, w1h);
    f2h_kernel<<<(DIM * DFF) / 1024, 256>>>(w2, w2h);

    // 1) QKV projection (fp16 out)
    gemm_f16<0,1><<<dim3(TD / 128, MR / 128), gblk, GSMEM_BYTES>>>(xh, wih, inb, qkvh, MR, TD, DIM);
    // 2) banded attention (fp16 in/out)
    attn_banded<<<BATCH * NH * (SEQ / 64), blk, ATT_SMEM>>>(qkvh, attnh, win);
    // 3) out projection (fp32 out)
    gemm_f16<0,0><<<dim3(DIM / 128, MR / 128), gblk, GSMEM_BYTES>>>(attnh, woh, ob, attnout, MR, DIM, DIM);
    // 4) x2 = LN1(x + attn_out)  (fp32 + fp16 out)
    add_ln_kernel<<<MR, blk>>>(x, attnout, l1g, l1b, x2, x2h);
    // 5) h = relu(x2 @ w1^T + b1) (fp16 out)
    gemm_f16<1,1><<<dim3(DFF / 128, MR / 128), gblk, GSMEM_BYTES>>>(x2h, w1h, b1, hh, MR, DFF, DIM);
    // 6) ff = h @ w2^T + b2 (fp32 out)
    gemm_f16<0,0><<<dim3(DIM / 128, MR / 128), gblk, GSMEM_BYTES>>>(hh, w2h, b2, ffb, MR, DIM, DFF);
    // 7) out = LN2(x2 + ff)
    add_ln_kernel<<<MR, blk>>>(x2, ffb, l2g, l2b, out, (__half*)0);
}